// round 11
// baseline (speedup 1.0000x reference)
#include <cuda_runtime.h>
#include <cuda_bf16.h>
#include <cstdint>

typedef unsigned long long ull;

#define NB 256
#define NT 512
#define NH 128
#define NG3 384

// ---------------- static scratch ----------------
__device__ float g_gx[(size_t)NB * NT * NG3];
__device__ float g_hseq[(size_t)NB * NT * NH];

// ---------------- helpers ----------------
__device__ __forceinline__ uint32_t smem_u32(const void* p) {
    uint32_t a;
    asm("{ .reg .u64 t; cvta.to.shared.u64 t, %1; cvt.u32.u64 %0, t; }" : "=r"(a) : "l"(p));
    return a;
}
// xor-swizzled byte offset in a [128][64] bf16 tile (16B chunks permuted by row&7)
__device__ __forceinline__ int swoff64(int row, int k) {
    return row * 128 + ((((k >> 3) ^ (row & 7)) << 4) | ((k & 7) << 1));
}
__device__ __forceinline__ uint32_t bf2_bits(float a, float b) {
    __nv_bfloat162 h = __floats2bfloat162_rn(a, b);
    return *reinterpret_cast<uint32_t*>(&h);
}
__device__ __forceinline__ ull ffma2(ull a, ull b, ull c) {
    ull d;
    asm("fma.rn.f32x2 %0, %1, %2, %3;" : "=l"(d) : "l"(a), "l"(b), "l"(c));
    return d;
}
__device__ __forceinline__ float f32x2_sum(ull a) {
    float lo, hi;
    asm("mov.b64 {%0, %1}, %2;" : "=f"(lo), "=f"(hi) : "l"(a));
    return lo + hi;
}
__device__ __forceinline__ ull pack2(float lo, float hi) {
    ull u;
    asm("mov.b64 %0, {%1, %2};" : "=l"(u) : "f"(lo), "f"(hi));
    return u;
}
__device__ __forceinline__ float tanhapx(float x) {
    float y;
    asm("tanh.approx.f32 %0, %1;" : "=f"(y) : "f"(x));
    return y;
}

__device__ __forceinline__ void ldsm_x4(uint32_t* r, uint32_t addr) {
    asm volatile("ldmatrix.sync.aligned.m8n8.x4.shared.b16 {%0,%1,%2,%3}, [%4];"
                 : "=r"(r[0]), "=r"(r[1]), "=r"(r[2]), "=r"(r[3]) : "r"(addr));
}
__device__ __forceinline__ void ldsm_x2(uint32_t* r, uint32_t addr) {
    asm volatile("ldmatrix.sync.aligned.m8n8.x2.shared.b16 {%0,%1}, [%2];"
                 : "=r"(r[0]), "=r"(r[1]) : "r"(addr));
}
__device__ __forceinline__ void mma_bf16(float* c, const uint32_t* a, const uint32_t* b) {
    asm volatile(
        "mma.sync.aligned.m16n8k16.row.col.f32.bf16.bf16.f32 "
        "{%0,%1,%2,%3}, {%4,%5,%6,%7}, {%8,%9}, {%0,%1,%2,%3};"
        : "+f"(c[0]), "+f"(c[1]), "+f"(c[2]), "+f"(c[3])
        : "r"(a[0]), "r"(a[1]), "r"(a[2]), "r"(a[3]), "r"(b[0]), "r"(b[1]));
}

// ---------------- gx GEMM: g_gx[m,384] = A[m,K] @ W^T + b_ih ----------------
// 3-product split-bf16 on mma.sync. CTA tile 128x128, K chunked by 64 so smem
// = 4 x 16KB = 64KB -> 2 CTAs/SM: one CTA's load/convert overlaps the other's mma.
template <int K>
__global__ __launch_bounds__(256, 2)
void gemm_mma(const float* __restrict__ A, const float* __restrict__ W,
              const float* __restrict__ bih) {
    constexpr int CK = 64;                 // k-chunk
    constexpr int TILE = 128 * CK * 2;     // 16384 B per bf16 tile
    extern __shared__ char sm[];
    char* Ahi = sm;
    char* Alo = Ahi + TILE;
    char* Whi = Alo + TILE;
    char* Wlo = Whi + TILE;

    const int tid = threadIdx.x;
    const int wid = tid >> 5, lane = tid & 31;
    const int mb = blockIdx.x, nb = blockIdx.y;
    const int warp_m = wid >> 2;           // 0..1  (64 rows each)
    const int warp_n = wid & 3;            // 0..3  (32 cols each)

    float acc[4][4][4];
    #pragma unroll
    for (int i = 0; i < 4; ++i)
        #pragma unroll
        for (int j = 0; j < 4; ++j)
            #pragma unroll
            for (int q = 0; q < 4; ++q) acc[i][j][q] = 0.f;

    const float4* Ag = reinterpret_cast<const float4*>(A + (size_t)mb * 128 * K);
    const float4* Wg = reinterpret_cast<const float4*>(W + (size_t)nb * 128 * K);

    #pragma unroll
    for (int c = 0; c < K / CK; ++c) {
        // ---- load + split chunk: A rows [0,128) x k [c*64, c*64+64), ditto W ----
        #pragma unroll
        for (int p = 0; p < 8; ++p) {       // 2048 float4 / 256 threads
            int idx = tid + p * 256;
            int m  = idx >> 4;              // row
            int kq = idx & 15;              // float4 index within chunk (k = kq*4)
            int sw = swoff64(m, kq * 4);
            {
                float4 v = Ag[(size_t)m * (K / 4) + c * 16 + kq];
                float h0 = __bfloat162float(__float2bfloat16(v.x));
                float h1 = __bfloat162float(__float2bfloat16(v.y));
                float h2 = __bfloat162float(__float2bfloat16(v.z));
                float h3 = __bfloat162float(__float2bfloat16(v.w));
                *reinterpret_cast<uint2*>(Ahi + sw) =
                    make_uint2(bf2_bits(v.x, v.y), bf2_bits(v.z, v.w));
                *reinterpret_cast<uint2*>(Alo + sw) =
                    make_uint2(bf2_bits(v.x - h0, v.y - h1), bf2_bits(v.z - h2, v.w - h3));
            }
            {
                float4 v = Wg[(size_t)m * (K / 4) + c * 16 + kq];
                float h0 = __bfloat162float(__float2bfloat16(v.x));
                float h1 = __bfloat162float(__float2bfloat16(v.y));
                float h2 = __bfloat162float(__float2bfloat16(v.z));
                float h3 = __bfloat162float(__float2bfloat16(v.w));
                *reinterpret_cast<uint2*>(Whi + sw) =
                    make_uint2(bf2_bits(v.x, v.y), bf2_bits(v.z, v.w));
                *reinterpret_cast<uint2*>(Wlo + sw) =
                    make_uint2(bf2_bits(v.x - h0, v.y - h1), bf2_bits(v.z - h2, v.w - h3));
            }
        }
        __syncthreads();

        const char* Abufs[3] = { Ahi, Alo, Ahi };   // (Ahi*Wlo)+(Alo*Whi)+(Ahi*Whi)
        const char* Wbufs[3] = { Wlo, Whi, Whi };
        #pragma unroll
        for (int s = 0; s < 3; ++s) {
            const char* Ab = Abufs[s];
            const char* Wb = Wbufs[s];
            #pragma unroll
            for (int kk = 0; kk < CK / 16; ++kk) {
                const int kb = kk * 16;
                uint32_t af[4][4], bf[4][2];
                #pragma unroll
                for (int mf = 0; mf < 4; ++mf) {
                    int row = warp_m * 64 + mf * 16 + (lane & 15);
                    ldsm_x4(af[mf], smem_u32(Ab + swoff64(row, kb + (lane >> 4) * 8)));
                }
                #pragma unroll
                for (int nf = 0; nf < 4; ++nf) {
                    int rn = warp_n * 32 + nf * 8 + (lane & 7);
                    ldsm_x2(bf[nf], smem_u32(Wb + swoff64(rn, kb + ((lane >> 3) & 1) * 8)));
                }
                #pragma unroll
                for (int mf = 0; mf < 4; ++mf)
                    #pragma unroll
                    for (int nf = 0; nf < 4; ++nf)
                        mma_bf16(acc[mf][nf], af[mf], bf[nf]);
            }
        }
        __syncthreads();    // all warps done with smem before next chunk's stores
    }

    // ---- epilogue: D + bias -> g_gx ----
    const int gr = lane >> 2, gc = (lane & 3) * 2;
    float bv[4][2];
    #pragma unroll
    for (int nf = 0; nf < 4; ++nf) {
        int col = nb * 128 + warp_n * 32 + nf * 8 + gc;
        bv[nf][0] = bih[col];
        bv[nf][1] = bih[col + 1];
    }
    #pragma unroll
    for (int mf = 0; mf < 4; ++mf) {
        int m0 = mb * 128 + warp_m * 64 + mf * 16 + gr;
        #pragma unroll
        for (int nf = 0; nf < 4; ++nf) {
            int col = nb * 128 + warp_n * 32 + nf * 8 + gc;
            float2 v0 = make_float2(acc[mf][nf][0] + bv[nf][0], acc[mf][nf][1] + bv[nf][1]);
            float2 v1 = make_float2(acc[mf][nf][2] + bv[nf][0], acc[mf][nf][3] + bv[nf][1]);
            *reinterpret_cast<float2*>(g_gx + (size_t)m0 * NG3 + col) = v0;
            *reinterpret_cast<float2*>(g_gx + (size_t)(m0 + 8) * NG3 + col) = v1;
        }
    }
}

// ---------------- GRU scan: warp-internal k-split (exact R10 version) ----------------
#define HSEG 40   // padded segment stride (floats): bases hit banks 0/8/16/24
__global__ __launch_bounds__(384, 1)
void gru_scan_kernel(const float* __restrict__ whh, const float* __restrict__ bhh) {
    __shared__ __align__(16) float h0s[4 * HSEG];
    __shared__ __align__(16) float h1s[4 * HSEG];
    __shared__ __align__(16) float accs[2 * NG3];

    const int tid  = threadIdx.x;
    const int wid  = tid >> 5, lane = tid & 31;
    const int kseg = lane & 3;
    const int row0 = wid * 32 + (lane >> 2) * 4;
    const int b0   = blockIdx.x * 2;

    ull wreg[4][16];
    #pragma unroll
    for (int rr = 0; rr < 4; ++rr) {
        const float4* wp = reinterpret_cast<const float4*>(
            whh + (size_t)(row0 + rr) * NH + kseg * 32);
        #pragma unroll
        for (int f = 0; f < 8; ++f) {
            float4 v = wp[f];
            wreg[rr][2 * f]     = pack2(v.x, v.y);
            wreg[rr][2 * f + 1] = pack2(v.z, v.w);
        }
    }
    float bias[4];
    #pragma unroll
    for (int rr = 0; rr < 4; ++rr) bias[rr] = (kseg == 0) ? bhh[row0 + rr] : 0.f;

    const int ub = tid >> 7, uj = tid & 127;
    const int hoff = (uj >> 5) * HSEG + (uj & 31);
    const float* gp   = g_gx   + ((size_t)(b0 + ub) * NT) * NG3 + uj;
    float*       hout = g_hseq + ((size_t)(b0 + ub) * NT) * NH  + uj;
    float gr = 0.f, gz = 0.f, gn = 0.f, hprev = 0.f;
    if (tid < 256) {
        if (ub == 0) h0s[hoff] = 0.f; else h1s[hoff] = 0.f;
        gr = gp[0]; gz = gp[128]; gn = gp[256];
    }
    __syncthreads();

    const ulonglong2* p0 = reinterpret_cast<const ulonglong2*>(h0s + kseg * HSEG);
    const ulonglong2* p1 = reinterpret_cast<const ulonglong2*>(h1s + kseg * HSEG);

    for (int t = 0; t < NT; ++t) {
        float s0[4], s1[4];
        {
            ull a[4] = {0ULL, 0ULL, 0ULL, 0ULL};
            #pragma unroll
            for (int j = 0; j < 8; ++j) {
                ulonglong2 v = p0[j];
                #pragma unroll
                for (int rr = 0; rr < 4; ++rr) {
                    a[rr] = ffma2(wreg[rr][2 * j],     v.x, a[rr]);
                    a[rr] = ffma2(wreg[rr][2 * j + 1], v.y, a[rr]);
                }
            }
            #pragma unroll
            for (int rr = 0; rr < 4; ++rr) {
                float s = f32x2_sum(a[rr]);
                s += __shfl_xor_sync(0xffffffffu, s, 1);
                s += __shfl_xor_sync(0xffffffffu, s, 2);
                s0[rr] = s + bias[rr];
            }
        }
        {
            ull a[4] = {0ULL, 0ULL, 0ULL, 0ULL};
            #pragma unroll
            for (int j = 0; j < 8; ++j) {
                ulonglong2 v = p1[j];
                #pragma unroll
                for (int rr = 0; rr < 4; ++rr) {
                    a[rr] = ffma2(wreg[rr][2 * j],     v.x, a[rr]);
                    a[rr] = ffma2(wreg[rr][2 * j + 1], v.y, a[rr]);
                }
            }
            #pragma unroll
            for (int rr = 0; rr < 4; ++rr) {
                float s = f32x2_sum(a[rr]);
                s += __shfl_xor_sync(0xffffffffu, s, 1);
                s += __shfl_xor_sync(0xffffffffu, s, 2);
                s1[rr] = s + bias[rr];
            }
        }
        if (kseg == 0) {
            *reinterpret_cast<float4*>(accs + row0)       = make_float4(s0[0], s0[1], s0[2], s0[3]);
            *reinterpret_cast<float4*>(accs + NG3 + row0) = make_float4(s1[0], s1[1], s1[2], s1[3]);
        }
        __syncthreads();

        if (tid < 256) {
            const float* ac = accs + ub * NG3;
            float r = 0.5f * tanhapx(0.5f * (gr + ac[uj]))       + 0.5f;
            float z = 0.5f * tanhapx(0.5f * (gz + ac[128 + uj])) + 0.5f;
            float n = tanhapx(gn + r * ac[256 + uj]);
            float hn = n + z * (hprev - n);
            hprev = hn;
            hout[(size_t)t * NH] = hn;
            if (ub == 0) h0s[hoff] = hn; else h1s[hoff] = hn;
            if (t + 1 < NT) {
                const float* g2 = gp + (size_t)(t + 1) * NG3;
                gr = g2[0]; gz = g2[128]; gn = g2[256];
            }
        }
        __syncthreads();
    }
}

// ---------------- final FC ----------------
__global__ void fc_kernel(const float* __restrict__ fcw, const float* __restrict__ fcb,
                          float* __restrict__ out) {
    int b = blockIdx.x;
    int w = threadIdx.x >> 5;
    int lane = threadIdx.x & 31;
    if (w >= 6) return;
    const float* last = g_hseq + ((size_t)b * NT + NT - 1) * NH;
    float s = 0.f;
    #pragma unroll
    for (int k = 0; k < 4; ++k) {
        int j = lane + 32 * k;
        s += last[j] * fcw[w * NH + j];
    }
    #pragma unroll
    for (int o = 16; o; o >>= 1) s += __shfl_down_sync(0xffffffffu, s, o);
    if (lane == 0) out[b * 6 + w] = s + fcb[w];
}

// ---------------- launch ----------------
extern "C" void kernel_launch(void* const* d_in, const int* in_sizes, int n_in,
                              void* d_out, int out_size) {
    const float* x    = (const float*)d_in[0];
    const float* wih0 = (const float*)d_in[1];
    const float* wih1 = (const float*)d_in[2];
    const float* wih2 = (const float*)d_in[3];
    const float* whh  = (const float*)d_in[4];
    const float* bih  = (const float*)d_in[5];
    const float* bhh  = (const float*)d_in[6];
    const float* fcw  = (const float*)d_in[7];
    const float* fcb  = (const float*)d_in[8];
    float* out = (float*)d_out;

    constexpr int SMEM = 4 * 128 * 64 * 2;   // 65536 (per chunk, both K)
    cudaFuncSetAttribute(gemm_mma<64>,  cudaFuncAttributeMaxDynamicSharedMemorySize, SMEM);
    cudaFuncSetAttribute(gemm_mma<128>, cudaFuncAttributeMaxDynamicSharedMemorySize, SMEM);

    float* g_hseq_ptr = nullptr;
    cudaGetSymbolAddress((void**)&g_hseq_ptr, g_hseq);

    dim3 ggrid(NB * NT / 128, 3);

    gemm_mma<64><<<ggrid, 256, SMEM>>>(x, wih0, bih + 0 * NG3);                   // 1
    gru_scan_kernel<<<NB / 2, 384>>>(whh + 0 * NG3 * NH, bhh + 0 * NG3);          // 2
    gemm_mma<128><<<ggrid, 256, SMEM>>>(g_hseq_ptr, wih1, bih + 1 * NG3);         // 3
    gru_scan_kernel<<<NB / 2, 384>>>(whh + 1 * NG3 * NH, bhh + 1 * NG3);          // 4
    gemm_mma<128><<<ggrid, 256, SMEM>>>(g_hseq_ptr, wih2, bih + 2 * NG3);         // 5
    gru_scan_kernel<<<NB / 2, 384>>>(whh + 2 * NG3 * NH, bhh + 2 * NG3);          // 6 (ncu -s 5 target)
    fc_kernel<<<NB, 192>>>(fcw, fcb, out);                                        // 7
}

// round 12
// speedup vs baseline: 1.0179x; 1.0179x over previous
#include <cuda_runtime.h>
#include <cuda_bf16.h>
#include <cstdint>

typedef unsigned long long ull;

#define NB 256
#define NT 512
#define NH 128
#define NG3 384

// ---------------- static scratch ----------------
__device__ float g_gx[(size_t)NB * NT * NG3];
__device__ float g_hseq[(size_t)NB * NT * NH];

// ---------------- helpers ----------------
__device__ __forceinline__ uint32_t smem_u32(const void* p) {
    uint32_t a;
    asm("{ .reg .u64 t; cvta.to.shared.u64 t, %1; cvt.u32.u64 %0, t; }" : "=r"(a) : "l"(p));
    return a;
}
// xor-swizzled byte offset for a [128][K] bf16 tile: 16B chunks permuted by row&7
__device__ __forceinline__ int swoff(int row, int k, int K) {
    return row * K * 2 + ((((k >> 3) ^ (row & 7)) << 4) | ((k & 7) << 1));
}
__device__ __forceinline__ uint32_t bf2_bits(float a, float b) {
    __nv_bfloat162 h = __floats2bfloat162_rn(a, b);
    return *reinterpret_cast<uint32_t*>(&h);
}
__device__ __forceinline__ ull ffma2(ull a, ull b, ull c) {
    ull d;
    asm("fma.rn.f32x2 %0, %1, %2, %3;" : "=l"(d) : "l"(a), "l"(b), "l"(c));
    return d;
}
__device__ __forceinline__ float f32x2_sum(ull a) {
    float lo, hi;
    asm("mov.b64 {%0, %1}, %2;" : "=f"(lo), "=f"(hi) : "l"(a));
    return lo + hi;
}
__device__ __forceinline__ ull pack2(float lo, float hi) {
    ull u;
    asm("mov.b64 %0, {%1, %2};" : "=l"(u) : "f"(lo), "f"(hi));
    return u;
}
__device__ __forceinline__ float tanhapx(float x) {
    float y;
    asm("tanh.approx.f32 %0, %1;" : "=f"(y) : "f"(x));
    return y;
}

__device__ __forceinline__ void ldsm_x4(uint32_t* r, uint32_t addr) {
    asm volatile("ldmatrix.sync.aligned.m8n8.x4.shared.b16 {%0,%1,%2,%3}, [%4];"
                 : "=r"(r[0]), "=r"(r[1]), "=r"(r[2]), "=r"(r[3]) : "r"(addr));
}
__device__ __forceinline__ void ldsm_x2(uint32_t* r, uint32_t addr) {
    asm volatile("ldmatrix.sync.aligned.m8n8.x2.shared.b16 {%0,%1}, [%2];"
                 : "=r"(r[0]), "=r"(r[1]) : "r"(addr));
}
__device__ __forceinline__ void mma_bf16(float* c, const uint32_t* a, const uint32_t* b) {
    asm volatile(
        "mma.sync.aligned.m16n8k16.row.col.f32.bf16.bf16.f32 "
        "{%0,%1,%2,%3}, {%4,%5,%6,%7}, {%8,%9}, {%0,%1,%2,%3};"
        : "+f"(c[0]), "+f"(c[1]), "+f"(c[2]), "+f"(c[3])
        : "r"(a[0]), "r"(a[1]), "r"(a[2]), "r"(a[3]), "r"(b[0]), "r"(b[1]));
}

// ---------------- gx GEMM: g_gx[m,384] = A[m,K] @ W^T + b_ih ----------------
// A-resident variant: each CTA converts its 128-row A tile ONCE, keeps it in
// smem, and loops over the 3 N-slices (W tiles come from L2: W is only 196KB).
// A DRAM traffic and A conversion drop 3x vs the (1024,3) grid.
template <int K>
__global__ __launch_bounds__(256, 1)
void gemm_mma(const float* __restrict__ A, const float* __restrict__ W,
              const float* __restrict__ bih) {
    extern __shared__ char sm[];
    constexpr int TILE = 128 * K * 2;
    char* Ahi = sm;
    char* Alo = Ahi + TILE;
    char* Whi = Alo + TILE;
    char* Wlo = Whi + TILE;

    const int tid = threadIdx.x;
    const int wid = tid >> 5, lane = tid & 31;
    const int mb = blockIdx.x;
    const int warp_m = wid >> 2;        // 0..1  (64 rows each)
    const int warp_n = wid & 3;         // 0..3  (32 cols each)

    // ---- load + split A tile (once) ----
    {
        const float4* Ag = reinterpret_cast<const float4*>(A + (size_t)mb * 128 * K);
        #pragma unroll
        for (int p = 0; p < (128 * K / 4) / 256; ++p) {
            int idx = tid + p * 256;
            int m = idx / (K / 4);
            int k = (idx % (K / 4)) * 4;
            float4 v = Ag[idx];
            float h0 = __bfloat162float(__float2bfloat16(v.x));
            float h1 = __bfloat162float(__float2bfloat16(v.y));
            float h2 = __bfloat162float(__float2bfloat16(v.z));
            float h3 = __bfloat162float(__float2bfloat16(v.w));
            uint2 hi = make_uint2(bf2_bits(v.x, v.y), bf2_bits(v.z, v.w));
            uint2 lo = make_uint2(bf2_bits(v.x - h0, v.y - h1), bf2_bits(v.z - h2, v.w - h3));
            int sw = swoff(m, k, K);
            *reinterpret_cast<uint2*>(Ahi + sw) = hi;
            *reinterpret_cast<uint2*>(Alo + sw) = lo;
        }
    }

    // ---- loop over the 3 N-slices, W tile per pass ----
    for (int nb = 0; nb < 3; ++nb) {
        if (nb > 0) __syncthreads();    // prior pass done reading W smem
        {
            const float4* Wg = reinterpret_cast<const float4*>(W + (size_t)nb * 128 * K);
            #pragma unroll
            for (int p = 0; p < (128 * K / 4) / 256; ++p) {
                int idx = tid + p * 256;
                int n = idx / (K / 4);
                int k = (idx % (K / 4)) * 4;
                float4 v = Wg[idx];
                float h0 = __bfloat162float(__float2bfloat16(v.x));
                float h1 = __bfloat162float(__float2bfloat16(v.y));
                float h2 = __bfloat162float(__float2bfloat16(v.z));
                float h3 = __bfloat162float(__float2bfloat16(v.w));
                uint2 hi = make_uint2(bf2_bits(v.x, v.y), bf2_bits(v.z, v.w));
                uint2 lo = make_uint2(bf2_bits(v.x - h0, v.y - h1), bf2_bits(v.z - h2, v.w - h3));
                int sw = swoff(n, k, K);
                *reinterpret_cast<uint2*>(Whi + sw) = hi;
                *reinterpret_cast<uint2*>(Wlo + sw) = lo;
            }
        }
        __syncthreads();                // A (pass 0) + W stores visible

        float acc[4][4][4];
        #pragma unroll
        for (int i = 0; i < 4; ++i)
            #pragma unroll
            for (int j = 0; j < 4; ++j)
                #pragma unroll
                for (int q = 0; q < 4; ++q) acc[i][j][q] = 0.f;

        const char* Abufs[3] = { Ahi, Alo, Ahi };   // (Ahi*Wlo)+(Alo*Whi)+(Ahi*Whi)
        const char* Wbufs[3] = { Wlo, Whi, Whi };

        #pragma unroll
        for (int s = 0; s < 3; ++s) {
            const char* Ab = Abufs[s];
            const char* Wb = Wbufs[s];
            #pragma unroll
            for (int kk = 0; kk < K / 16; ++kk) {
                const int kb = kk * 16;
                uint32_t af[4][4], bf[4][2];
                #pragma unroll
                for (int mf = 0; mf < 4; ++mf) {
                    int row = warp_m * 64 + mf * 16 + (lane & 15);
                    ldsm_x4(af[mf], smem_u32(Ab + swoff(row, kb + (lane >> 4) * 8, K)));
                }
                #pragma unroll
                for (int nf = 0; nf < 4; ++nf) {
                    int rn = warp_n * 32 + nf * 8 + (lane & 7);
                    ldsm_x2(bf[nf], smem_u32(Wb + swoff(rn, kb + ((lane >> 3) & 1) * 8, K)));
                }
                #pragma unroll
                for (int mf = 0; mf < 4; ++mf)
                    #pragma unroll
                    for (int nf = 0; nf < 4; ++nf)
                        mma_bf16(acc[mf][nf], af[mf], bf[nf]);
            }
        }

        // ---- epilogue: D + bias -> g_gx slice nb (regs only, no sync needed) ----
        const int gr = lane >> 2, gc = (lane & 3) * 2;
        float bv[4][2];
        #pragma unroll
        for (int nf = 0; nf < 4; ++nf) {
            int col = nb * 128 + warp_n * 32 + nf * 8 + gc;
            bv[nf][0] = bih[col];
            bv[nf][1] = bih[col + 1];
        }
        #pragma unroll
        for (int mf = 0; mf < 4; ++mf) {
            int m0 = mb * 128 + warp_m * 64 + mf * 16 + gr;
            #pragma unroll
            for (int nf = 0; nf < 4; ++nf) {
                int col = nb * 128 + warp_n * 32 + nf * 8 + gc;
                float2 v0 = make_float2(acc[mf][nf][0] + bv[nf][0], acc[mf][nf][1] + bv[nf][1]);
                float2 v1 = make_float2(acc[mf][nf][2] + bv[nf][0], acc[mf][nf][3] + bv[nf][1]);
                *reinterpret_cast<float2*>(g_gx + (size_t)m0 * NG3 + col) = v0;
                *reinterpret_cast<float2*>(g_gx + (size_t)(m0 + 8) * NG3 + col) = v1;
            }
        }
    }
}

// ---------------- GRU scan: warp-internal k-split (exact R10 version) ----------------
#define HSEG 40   // padded segment stride (floats): bases hit banks 0/8/16/24
__global__ __launch_bounds__(384, 1)
void gru_scan_kernel(const float* __restrict__ whh, const float* __restrict__ bhh) {
    __shared__ __align__(16) float h0s[4 * HSEG];
    __shared__ __align__(16) float h1s[4 * HSEG];
    __shared__ __align__(16) float accs[2 * NG3];

    const int tid  = threadIdx.x;
    const int wid  = tid >> 5, lane = tid & 31;
    const int kseg = lane & 3;
    const int row0 = wid * 32 + (lane >> 2) * 4;
    const int b0   = blockIdx.x * 2;

    ull wreg[4][16];
    #pragma unroll
    for (int rr = 0; rr < 4; ++rr) {
        const float4* wp = reinterpret_cast<const float4*>(
            whh + (size_t)(row0 + rr) * NH + kseg * 32);
        #pragma unroll
        for (int f = 0; f < 8; ++f) {
            float4 v = wp[f];
            wreg[rr][2 * f]     = pack2(v.x, v.y);
            wreg[rr][2 * f + 1] = pack2(v.z, v.w);
        }
    }
    float bias[4];
    #pragma unroll
    for (int rr = 0; rr < 4; ++rr) bias[rr] = (kseg == 0) ? bhh[row0 + rr] : 0.f;

    const int ub = tid >> 7, uj = tid & 127;
    const int hoff = (uj >> 5) * HSEG + (uj & 31);
    const float* gp   = g_gx   + ((size_t)(b0 + ub) * NT) * NG3 + uj;
    float*       hout = g_hseq + ((size_t)(b0 + ub) * NT) * NH  + uj;
    float gr = 0.f, gz = 0.f, gn = 0.f, hprev = 0.f;
    if (tid < 256) {
        if (ub == 0) h0s[hoff] = 0.f; else h1s[hoff] = 0.f;
        gr = gp[0]; gz = gp[128]; gn = gp[256];
    }
    __syncthreads();

    const ulonglong2* p0 = reinterpret_cast<const ulonglong2*>(h0s + kseg * HSEG);
    const ulonglong2* p1 = reinterpret_cast<const ulonglong2*>(h1s + kseg * HSEG);

    for (int t = 0; t < NT; ++t) {
        float s0[4], s1[4];
        {
            ull a[4] = {0ULL, 0ULL, 0ULL, 0ULL};
            #pragma unroll
            for (int j = 0; j < 8; ++j) {
                ulonglong2 v = p0[j];
                #pragma unroll
                for (int rr = 0; rr < 4; ++rr) {
                    a[rr] = ffma2(wreg[rr][2 * j],     v.x, a[rr]);
                    a[rr] = ffma2(wreg[rr][2 * j + 1], v.y, a[rr]);
                }
            }
            #pragma unroll
            for (int rr = 0; rr < 4; ++rr) {
                float s = f32x2_sum(a[rr]);
                s += __shfl_xor_sync(0xffffffffu, s, 1);
                s += __shfl_xor_sync(0xffffffffu, s, 2);
                s0[rr] = s + bias[rr];
            }
        }
        {
            ull a[4] = {0ULL, 0ULL, 0ULL, 0ULL};
            #pragma unroll
            for (int j = 0; j < 8; ++j) {
                ulonglong2 v = p1[j];
                #pragma unroll
                for (int rr = 0; rr < 4; ++rr) {
                    a[rr] = ffma2(wreg[rr][2 * j],     v.x, a[rr]);
                    a[rr] = ffma2(wreg[rr][2 * j + 1], v.y, a[rr]);
                }
            }
            #pragma unroll
            for (int rr = 0; rr < 4; ++rr) {
                float s = f32x2_sum(a[rr]);
                s += __shfl_xor_sync(0xffffffffu, s, 1);
                s += __shfl_xor_sync(0xffffffffu, s, 2);
                s1[rr] = s + bias[rr];
            }
        }
        if (kseg == 0) {
            *reinterpret_cast<float4*>(accs + row0)       = make_float4(s0[0], s0[1], s0[2], s0[3]);
            *reinterpret_cast<float4*>(accs + NG3 + row0) = make_float4(s1[0], s1[1], s1[2], s1[3]);
        }
        __syncthreads();

        if (tid < 256) {
            const float* ac = accs + ub * NG3;
            float r = 0.5f * tanhapx(0.5f * (gr + ac[uj]))       + 0.5f;
            float z = 0.5f * tanhapx(0.5f * (gz + ac[128 + uj])) + 0.5f;
            float n = tanhapx(gn + r * ac[256 + uj]);
            float hn = n + z * (hprev - n);
            hprev = hn;
            hout[(size_t)t * NH] = hn;
            if (ub == 0) h0s[hoff] = hn; else h1s[hoff] = hn;
            if (t + 1 < NT) {
                const float* g2 = gp + (size_t)(t + 1) * NG3;
                gr = g2[0]; gz = g2[128]; gn = g2[256];
            }
        }
        __syncthreads();
    }
}

// ---------------- final FC ----------------
__global__ void fc_kernel(const float* __restrict__ fcw, const float* __restrict__ fcb,
                          float* __restrict__ out) {
    int b = blockIdx.x;
    int w = threadIdx.x >> 5;
    int lane = threadIdx.x & 31;
    if (w >= 6) return;
    const float* last = g_hseq + ((size_t)b * NT + NT - 1) * NH;
    float s = 0.f;
    #pragma unroll
    for (int k = 0; k < 4; ++k) {
        int j = lane + 32 * k;
        s += last[j] * fcw[w * NH + j];
    }
    #pragma unroll
    for (int o = 16; o; o >>= 1) s += __shfl_down_sync(0xffffffffu, s, o);
    if (lane == 0) out[b * 6 + w] = s + fcb[w];
}

// ---------------- launch-slot filler so ncu -s 5 captures gemm layer 2 ----------------
__global__ void noop_kernel() {}

// ---------------- launch ----------------
extern "C" void kernel_launch(void* const* d_in, const int* in_sizes, int n_in,
                              void* d_out, int out_size) {
    const float* x    = (const float*)d_in[0];
    const float* wih0 = (const float*)d_in[1];
    const float* wih1 = (const float*)d_in[2];
    const float* wih2 = (const float*)d_in[3];
    const float* whh  = (const float*)d_in[4];
    const float* bih  = (const float*)d_in[5];
    const float* bhh  = (const float*)d_in[6];
    const float* fcw  = (const float*)d_in[7];
    const float* fcb  = (const float*)d_in[8];
    float* out = (float*)d_out;

    constexpr int SMEM64  = 4 * 128 * 64 * 2;    //  65536
    constexpr int SMEM128 = 4 * 128 * 128 * 2;   // 131072
    cudaFuncSetAttribute(gemm_mma<64>,  cudaFuncAttributeMaxDynamicSharedMemorySize, SMEM64);
    cudaFuncSetAttribute(gemm_mma<128>, cudaFuncAttributeMaxDynamicSharedMemorySize, SMEM128);

    float* g_hseq_ptr = nullptr;
    cudaGetSymbolAddress((void**)&g_hseq_ptr, g_hseq);

    const int ggrid = NB * NT / 128;   // 1024 CTAs, each covers all 384 N cols

    gemm_mma<64><<<ggrid, 256, SMEM64>>>(x, wih0, bih + 0 * NG3);                 // 1
    gru_scan_kernel<<<NB / 2, 384>>>(whh + 0 * NG3 * NH, bhh + 0 * NG3);          // 2
    gemm_mma<128><<<ggrid, 256, SMEM128>>>(g_hseq_ptr, wih1, bih + 1 * NG3);      // 3
    gru_scan_kernel<<<NB / 2, 384>>>(whh + 1 * NG3 * NH, bhh + 1 * NG3);          // 4
    noop_kernel<<<1, 32>>>();                                                     // 5 (slot filler)
    gemm_mma<128><<<ggrid, 256, SMEM128>>>(g_hseq_ptr, wih2, bih + 2 * NG3);      // 6 (ncu -s 5 target)
    gru_scan_kernel<<<NB / 2, 384>>>(whh + 2 * NG3 * NH, bhh + 2 * NG3);          // 7
    fc_kernel<<<NB, 192>>>(fcw, fcb, out);                                        // 8
}

// round 13
// speedup vs baseline: 1.0325x; 1.0144x over previous
#include <cuda_runtime.h>
#include <cuda_bf16.h>
#include <cstdint>

typedef unsigned long long ull;

#define NB 256
#define NT 512
#define NH 128
#define NG3 384

// ---------------- static scratch ----------------
__device__ float g_gx[(size_t)NB * NT * NG3];
__device__ float g_hseq[(size_t)NB * NT * NH];

// ---------------- helpers ----------------
__device__ __forceinline__ uint32_t smem_u32(const void* p) {
    uint32_t a;
    asm("{ .reg .u64 t; cvta.to.shared.u64 t, %1; cvt.u32.u64 %0, t; }" : "=r"(a) : "l"(p));
    return a;
}
// xor-swizzled byte offset for a [128][K] bf16 tile: 16B chunks permuted by row&7
__device__ __forceinline__ int swoff(int row, int k, int K) {
    return row * K * 2 + ((((k >> 3) ^ (row & 7)) << 4) | ((k & 7) << 1));
}
__device__ __forceinline__ uint32_t bf2_bits(float a, float b) {
    __nv_bfloat162 h = __floats2bfloat162_rn(a, b);
    return *reinterpret_cast<uint32_t*>(&h);
}
__device__ __forceinline__ ull ffma2(ull a, ull b, ull c) {
    ull d;
    asm("fma.rn.f32x2 %0, %1, %2, %3;" : "=l"(d) : "l"(a), "l"(b), "l"(c));
    return d;
}
__device__ __forceinline__ float f32x2_sum(ull a) {
    float lo, hi;
    asm("mov.b64 {%0, %1}, %2;" : "=f"(lo), "=f"(hi) : "l"(a));
    return lo + hi;
}
__device__ __forceinline__ ull pack2(float lo, float hi) {
    ull u;
    asm("mov.b64 %0, {%1, %2};" : "=l"(u) : "f"(lo), "f"(hi));
    return u;
}
__device__ __forceinline__ float tanhapx(float x) {
    float y;
    asm("tanh.approx.f32 %0, %1;" : "=f"(y) : "f"(x));
    return y;
}

__device__ __forceinline__ void ldsm_x4(uint32_t* r, uint32_t addr) {
    asm volatile("ldmatrix.sync.aligned.m8n8.x4.shared.b16 {%0,%1,%2,%3}, [%4];"
                 : "=r"(r[0]), "=r"(r[1]), "=r"(r[2]), "=r"(r[3]) : "r"(addr));
}
__device__ __forceinline__ void ldsm_x2(uint32_t* r, uint32_t addr) {
    asm volatile("ldmatrix.sync.aligned.m8n8.x2.shared.b16 {%0,%1}, [%2];"
                 : "=r"(r[0]), "=r"(r[1]) : "r"(addr));
}
__device__ __forceinline__ void mma_bf16(float* c, const uint32_t* a, const uint32_t* b) {
    asm volatile(
        "mma.sync.aligned.m16n8k16.row.col.f32.bf16.bf16.f32 "
        "{%0,%1,%2,%3}, {%4,%5,%6,%7}, {%8,%9}, {%0,%1,%2,%3};"
        : "+f"(c[0]), "+f"(c[1]), "+f"(c[2]), "+f"(c[3])
        : "r"(a[0]), "r"(a[1]), "r"(a[2]), "r"(a[3]), "r"(b[0]), "r"(b[1]));
}

// ---------------- gx GEMM: g_gx[m,384] = A[m,K] @ W^T + b_ih ----------------
// A-resident variant: each CTA converts its 128-row A tile ONCE, keeps it in
// smem, and loops over the 3 N-slices (W tiles come from L2: W is only 196KB).
// A DRAM traffic and A conversion drop 3x vs the (1024,3) grid.
template <int K>
__global__ __launch_bounds__(256, 1)
void gemm_mma(const float* __restrict__ A, const float* __restrict__ W,
              const float* __restrict__ bih) {
    extern __shared__ char sm[];
    constexpr int TILE = 128 * K * 2;
    char* Ahi = sm;
    char* Alo = Ahi + TILE;
    char* Whi = Alo + TILE;
    char* Wlo = Whi + TILE;

    const int tid = threadIdx.x;
    const int wid = tid >> 5, lane = tid & 31;
    const int mb = blockIdx.x;
    const int warp_m = wid >> 2;        // 0..1  (64 rows each)
    const int warp_n = wid & 3;         // 0..3  (32 cols each)

    // ---- load + split A tile (once) ----
    {
        const float4* Ag = reinterpret_cast<const float4*>(A + (size_t)mb * 128 * K);
        #pragma unroll
        for (int p = 0; p < (128 * K / 4) / 256; ++p) {
            int idx = tid + p * 256;
            int m = idx / (K / 4);
            int k = (idx % (K / 4)) * 4;
            float4 v = Ag[idx];
            float h0 = __bfloat162float(__float2bfloat16(v.x));
            float h1 = __bfloat162float(__float2bfloat16(v.y));
            float h2 = __bfloat162float(__float2bfloat16(v.z));
            float h3 = __bfloat162float(__float2bfloat16(v.w));
            uint2 hi = make_uint2(bf2_bits(v.x, v.y), bf2_bits(v.z, v.w));
            uint2 lo = make_uint2(bf2_bits(v.x - h0, v.y - h1), bf2_bits(v.z - h2, v.w - h3));
            int sw = swoff(m, k, K);
            *reinterpret_cast<uint2*>(Ahi + sw) = hi;
            *reinterpret_cast<uint2*>(Alo + sw) = lo;
        }
    }

    // ---- loop over the 3 N-slices, W tile per pass ----
    for (int nb = 0; nb < 3; ++nb) {
        if (nb > 0) __syncthreads();    // prior pass done reading W smem
        {
            const float4* Wg = reinterpret_cast<const float4*>(W + (size_t)nb * 128 * K);
            #pragma unroll
            for (int p = 0; p < (128 * K / 4) / 256; ++p) {
                int idx = tid + p * 256;
                int n = idx / (K / 4);
                int k = (idx % (K / 4)) * 4;
                float4 v = Wg[idx];
                float h0 = __bfloat162float(__float2bfloat16(v.x));
                float h1 = __bfloat162float(__float2bfloat16(v.y));
                float h2 = __bfloat162float(__float2bfloat16(v.z));
                float h3 = __bfloat162float(__float2bfloat16(v.w));
                uint2 hi = make_uint2(bf2_bits(v.x, v.y), bf2_bits(v.z, v.w));
                uint2 lo = make_uint2(bf2_bits(v.x - h0, v.y - h1), bf2_bits(v.z - h2, v.w - h3));
                int sw = swoff(n, k, K);
                *reinterpret_cast<uint2*>(Whi + sw) = hi;
                *reinterpret_cast<uint2*>(Wlo + sw) = lo;
            }
        }
        __syncthreads();                // A (pass 0) + W stores visible

        float acc[4][4][4];
        #pragma unroll
        for (int i = 0; i < 4; ++i)
            #pragma unroll
            for (int j = 0; j < 4; ++j)
                #pragma unroll
                for (int q = 0; q < 4; ++q) acc[i][j][q] = 0.f;

        const char* Abufs[3] = { Ahi, Alo, Ahi };   // (Ahi*Wlo)+(Alo*Whi)+(Ahi*Whi)
        const char* Wbufs[3] = { Wlo, Whi, Whi };

        #pragma unroll
        for (int s = 0; s < 3; ++s) {
            const char* Ab = Abufs[s];
            const char* Wb = Wbufs[s];
            #pragma unroll
            for (int kk = 0; kk < K / 16; ++kk) {
                const int kb = kk * 16;
                uint32_t af[4][4], bf[4][2];
                #pragma unroll
                for (int mf = 0; mf < 4; ++mf) {
                    int row = warp_m * 64 + mf * 16 + (lane & 15);
                    ldsm_x4(af[mf], smem_u32(Ab + swoff(row, kb + (lane >> 4) * 8, K)));
                }
                #pragma unroll
                for (int nf = 0; nf < 4; ++nf) {
                    int rn = warp_n * 32 + nf * 8 + (lane & 7);
                    ldsm_x2(bf[nf], smem_u32(Wb + swoff(rn, kb + ((lane >> 3) & 1) * 8, K)));
                }
                #pragma unroll
                for (int mf = 0; mf < 4; ++mf)
                    #pragma unroll
                    for (int nf = 0; nf < 4; ++nf)
                        mma_bf16(acc[mf][nf], af[mf], bf[nf]);
            }
        }

        // ---- epilogue: D + bias -> g_gx slice nb (regs only, no sync needed) ----
        const int gr = lane >> 2, gc = (lane & 3) * 2;
        float bv[4][2];
        #pragma unroll
        for (int nf = 0; nf < 4; ++nf) {
            int col = nb * 128 + warp_n * 32 + nf * 8 + gc;
            bv[nf][0] = bih[col];
            bv[nf][1] = bih[col + 1];
        }
        #pragma unroll
        for (int mf = 0; mf < 4; ++mf) {
            int m0 = mb * 128 + warp_m * 64 + mf * 16 + gr;
            #pragma unroll
            for (int nf = 0; nf < 4; ++nf) {
                int col = nb * 128 + warp_n * 32 + nf * 8 + gc;
                float2 v0 = make_float2(acc[mf][nf][0] + bv[nf][0], acc[mf][nf][1] + bv[nf][1]);
                float2 v1 = make_float2(acc[mf][nf][2] + bv[nf][0], acc[mf][nf][3] + bv[nf][1]);
                *reinterpret_cast<float2*>(g_gx + (size_t)m0 * NG3 + col) = v0;
                *reinterpret_cast<float2*>(g_gx + (size_t)(m0 + 8) * NG3 + col) = v1;
            }
        }
    }
}

// ---------------- GRU scan: warp-internal k-split (exact R10 version) ----------------
#define HSEG 40   // padded segment stride (floats): bases hit banks 0/8/16/24
__global__ __launch_bounds__(384, 1)
void gru_scan_kernel(const float* __restrict__ whh, const float* __restrict__ bhh) {
    __shared__ __align__(16) float h0s[4 * HSEG];
    __shared__ __align__(16) float h1s[4 * HSEG];
    __shared__ __align__(16) float accs[2 * NG3];

    const int tid  = threadIdx.x;
    const int wid  = tid >> 5, lane = tid & 31;
    const int kseg = lane & 3;
    const int row0 = wid * 32 + (lane >> 2) * 4;
    const int b0   = blockIdx.x * 2;

    ull wreg[4][16];
    #pragma unroll
    for (int rr = 0; rr < 4; ++rr) {
        const float4* wp = reinterpret_cast<const float4*>(
            whh + (size_t)(row0 + rr) * NH + kseg * 32);
        #pragma unroll
        for (int f = 0; f < 8; ++f) {
            float4 v = wp[f];
            wreg[rr][2 * f]     = pack2(v.x, v.y);
            wreg[rr][2 * f + 1] = pack2(v.z, v.w);
        }
    }
    float bias[4];
    #pragma unroll
    for (int rr = 0; rr < 4; ++rr) bias[rr] = (kseg == 0) ? bhh[row0 + rr] : 0.f;

    const int ub = tid >> 7, uj = tid & 127;
    const int hoff = (uj >> 5) * HSEG + (uj & 31);
    const float* gp   = g_gx   + ((size_t)(b0 + ub) * NT) * NG3 + uj;
    float*       hout = g_hseq + ((size_t)(b0 + ub) * NT) * NH  + uj;
    float gr = 0.f, gz = 0.f, gn = 0.f, hprev = 0.f;
    if (tid < 256) {
        if (ub == 0) h0s[hoff] = 0.f; else h1s[hoff] = 0.f;
        gr = gp[0]; gz = gp[128]; gn = gp[256];
    }
    __syncthreads();

    const ulonglong2* p0 = reinterpret_cast<const ulonglong2*>(h0s + kseg * HSEG);
    const ulonglong2* p1 = reinterpret_cast<const ulonglong2*>(h1s + kseg * HSEG);

    for (int t = 0; t < NT; ++t) {
        float s0[4], s1[4];
        {
            ull a[4] = {0ULL, 0ULL, 0ULL, 0ULL};
            #pragma unroll
            for (int j = 0; j < 8; ++j) {
                ulonglong2 v = p0[j];
                #pragma unroll
                for (int rr = 0; rr < 4; ++rr) {
                    a[rr] = ffma2(wreg[rr][2 * j],     v.x, a[rr]);
                    a[rr] = ffma2(wreg[rr][2 * j + 1], v.y, a[rr]);
                }
            }
            #pragma unroll
            for (int rr = 0; rr < 4; ++rr) {
                float s = f32x2_sum(a[rr]);
                s += __shfl_xor_sync(0xffffffffu, s, 1);
                s += __shfl_xor_sync(0xffffffffu, s, 2);
                s0[rr] = s + bias[rr];
            }
        }
        {
            ull a[4] = {0ULL, 0ULL, 0ULL, 0ULL};
            #pragma unroll
            for (int j = 0; j < 8; ++j) {
                ulonglong2 v = p1[j];
                #pragma unroll
                for (int rr = 0; rr < 4; ++rr) {
                    a[rr] = ffma2(wreg[rr][2 * j],     v.x, a[rr]);
                    a[rr] = ffma2(wreg[rr][2 * j + 1], v.y, a[rr]);
                }
            }
            #pragma unroll
            for (int rr = 0; rr < 4; ++rr) {
                float s = f32x2_sum(a[rr]);
                s += __shfl_xor_sync(0xffffffffu, s, 1);
                s += __shfl_xor_sync(0xffffffffu, s, 2);
                s1[rr] = s + bias[rr];
            }
        }
        if (kseg == 0) {
            *reinterpret_cast<float4*>(accs + row0)       = make_float4(s0[0], s0[1], s0[2], s0[3]);
            *reinterpret_cast<float4*>(accs + NG3 + row0) = make_float4(s1[0], s1[1], s1[2], s1[3]);
        }
        __syncthreads();

        if (tid < 256) {
            const float* ac = accs + ub * NG3;
            float r = 0.5f * tanhapx(0.5f * (gr + ac[uj]))       + 0.5f;
            float z = 0.5f * tanhapx(0.5f * (gz + ac[128 + uj])) + 0.5f;
            float n = tanhapx(gn + r * ac[256 + uj]);
            float hn = n + z * (hprev - n);
            hprev = hn;
            hout[(size_t)t * NH] = hn;
            if (ub == 0) h0s[hoff] = hn; else h1s[hoff] = hn;
            if (t + 1 < NT) {
                const float* g2 = gp + (size_t)(t + 1) * NG3;
                gr = g2[0]; gz = g2[128]; gn = g2[256];
            }
        }
        __syncthreads();
    }
}

// ---------------- final FC ----------------
__global__ void fc_kernel(const float* __restrict__ fcw, const float* __restrict__ fcb,
                          float* __restrict__ out) {
    int b = blockIdx.x;
    int w = threadIdx.x >> 5;
    int lane = threadIdx.x & 31;
    if (w >= 6) return;
    const float* last = g_hseq + ((size_t)b * NT + NT - 1) * NH;
    float s = 0.f;
    #pragma unroll
    for (int k = 0; k < 4; ++k) {
        int j = lane + 32 * k;
        s += last[j] * fcw[w * NH + j];
    }
    #pragma unroll
    for (int o = 16; o; o >>= 1) s += __shfl_down_sync(0xffffffffu, s, o);
    if (lane == 0) out[b * 6 + w] = s + fcb[w];
}

// ---------------- launch-slot filler so ncu -s 5 captures gemm layer 2 ----------------
__global__ void noop_kernel() {}

// ---------------- launch ----------------
extern "C" void kernel_launch(void* const* d_in, const int* in_sizes, int n_in,
                              void* d_out, int out_size) {
    const float* x    = (const float*)d_in[0];
    const float* wih0 = (const float*)d_in[1];
    const float* wih1 = (const float*)d_in[2];
    const float* wih2 = (const float*)d_in[3];
    const float* whh  = (const float*)d_in[4];
    const float* bih  = (const float*)d_in[5];
    const float* bhh  = (const float*)d_in[6];
    const float* fcw  = (const float*)d_in[7];
    const float* fcb  = (const float*)d_in[8];
    float* out = (float*)d_out;

    constexpr int SMEM64  = 4 * 128 * 64 * 2;    //  65536
    constexpr int SMEM128 = 4 * 128 * 128 * 2;   // 131072
    cudaFuncSetAttribute(gemm_mma<64>,  cudaFuncAttributeMaxDynamicSharedMemorySize, SMEM64);
    cudaFuncSetAttribute(gemm_mma<128>, cudaFuncAttributeMaxDynamicSharedMemorySize, SMEM128);

    float* g_hseq_ptr = nullptr;
    cudaGetSymbolAddress((void**)&g_hseq_ptr, g_hseq);

    const int ggrid = NB * NT / 128;   // 1024 CTAs, each covers all 384 N cols

    gemm_mma<64><<<ggrid, 256, SMEM64>>>(x, wih0, bih + 0 * NG3);                 // 1
    gru_scan_kernel<<<NB / 2, 384>>>(whh + 0 * NG3 * NH, bhh + 0 * NG3);          // 2
    gemm_mma<128><<<ggrid, 256, SMEM128>>>(g_hseq_ptr, wih1, bih + 1 * NG3);      // 3
    gru_scan_kernel<<<NB / 2, 384>>>(whh + 1 * NG3 * NH, bhh + 1 * NG3);          // 4
    noop_kernel<<<1, 32>>>();                                                     // 5 (slot filler)
    gemm_mma<128><<<ggrid, 256, SMEM128>>>(g_hseq_ptr, wih2, bih + 2 * NG3);      // 6 (ncu -s 5 target)
    gru_scan_kernel<<<NB / 2, 384>>>(whh + 2 * NG3 * NH, bhh + 2 * NG3);          // 7
    fc_kernel<<<NB, 192>>>(fcw, fcb, out);                                        // 8
}

// round 14
// speedup vs baseline: 1.0503x; 1.0172x over previous
#include <cuda_runtime.h>
#include <cuda_bf16.h>
#include <cstdint>

typedef unsigned long long ull;

#define NB 256
#define NT 512
#define NH 128
#define NG3 384

// ---------------- static scratch ----------------
__device__ float g_gx[(size_t)NB * NT * NG3];
__device__ float g_hseq[(size_t)NB * NT * NH];

// ---------------- helpers ----------------
__device__ __forceinline__ uint32_t smem_u32(const void* p) {
    uint32_t a;
    asm("{ .reg .u64 t; cvta.to.shared.u64 t, %1; cvt.u32.u64 %0, t; }" : "=r"(a) : "l"(p));
    return a;
}
// xor-swizzled byte offset for a [128][K] bf16 tile: 16B chunks permuted by row&7
__device__ __forceinline__ int swoff(int row, int k, int K) {
    return row * K * 2 + ((((k >> 3) ^ (row & 7)) << 4) | ((k & 7) << 1));
}
__device__ __forceinline__ uint32_t bf2_bits(float a, float b) {
    __nv_bfloat162 h = __floats2bfloat162_rn(a, b);
    return *reinterpret_cast<uint32_t*>(&h);
}
__device__ __forceinline__ ull ffma2(ull a, ull b, ull c) {
    ull d;
    asm("fma.rn.f32x2 %0, %1, %2, %3;" : "=l"(d) : "l"(a), "l"(b), "l"(c));
    return d;
}
__device__ __forceinline__ float f32x2_sum(ull a) {
    float lo, hi;
    asm("mov.b64 {%0, %1}, %2;" : "=f"(lo), "=f"(hi) : "l"(a));
    return lo + hi;
}
__device__ __forceinline__ ull pack2(float lo, float hi) {
    ull u;
    asm("mov.b64 %0, {%1, %2};" : "=l"(u) : "f"(lo), "f"(hi));
    return u;
}
__device__ __forceinline__ float tanhapx(float x) {
    float y;
    asm("tanh.approx.f32 %0, %1;" : "=f"(y) : "f"(x));
    return y;
}

__device__ __forceinline__ void ldsm_x4(uint32_t* r, uint32_t addr) {
    asm volatile("ldmatrix.sync.aligned.m8n8.x4.shared.b16 {%0,%1,%2,%3}, [%4];"
                 : "=r"(r[0]), "=r"(r[1]), "=r"(r[2]), "=r"(r[3]) : "r"(addr));
}
__device__ __forceinline__ void ldsm_x2(uint32_t* r, uint32_t addr) {
    asm volatile("ldmatrix.sync.aligned.m8n8.x2.shared.b16 {%0,%1}, [%2];"
                 : "=r"(r[0]), "=r"(r[1]) : "r"(addr));
}
__device__ __forceinline__ void mma_bf16(float* c, const uint32_t* a, const uint32_t* b) {
    asm volatile(
        "mma.sync.aligned.m16n8k16.row.col.f32.bf16.bf16.f32 "
        "{%0,%1,%2,%3}, {%4,%5,%6,%7}, {%8,%9}, {%0,%1,%2,%3};"
        : "+f"(c[0]), "+f"(c[1]), "+f"(c[2]), "+f"(c[3])
        : "r"(a[0]), "r"(a[1]), "r"(a[2]), "r"(a[3]), "r"(b[0]), "r"(b[1]));
}

// ---------------- gx GEMM: g_gx[m,384] = A[m,K] @ W^T + b_ih ----------------
// A-resident + double-buffered W + register prefetch + fragment-reuse mma loop.
// smem = A(hi,lo) + W(hi,lo) x 2 buffers = 6 tiles.
template <int K>
__global__ __launch_bounds__(256, 1)
void gemm_mma(const float* __restrict__ A, const float* __restrict__ W,
              const float* __restrict__ bih, int mb_off) {
    extern __shared__ char sm[];
    constexpr int TILE = 128 * K * 2;
    constexpr int NF4  = (128 * (K / 4)) / 256;    // float4 per thread per W tile
    char* Ahi = sm;
    char* Alo = Ahi + TILE;
    char* Wbuf[2][2] = { { Alo + TILE,            Alo + 2 * TILE },
                         { Alo + 3 * TILE,        Alo + 4 * TILE } };  // [buf][hi/lo]

    const int tid = threadIdx.x;
    const int wid = tid >> 5, lane = tid & 31;
    const int mb = blockIdx.x + mb_off;
    const int warp_m = wid >> 2;        // 0..1  (64 rows each)
    const int warp_n = wid & 3;         // 0..3  (32 cols each)

    // ---- load + split A tile (once) ----
    {
        const float4* Ag = reinterpret_cast<const float4*>(A + (size_t)mb * 128 * K);
        #pragma unroll
        for (int p = 0; p < NF4; ++p) {
            int idx = tid + p * 256;
            int m = idx / (K / 4);
            int k = (idx % (K / 4)) * 4;
            float4 v = Ag[idx];
            float h0 = __bfloat162float(__float2bfloat16(v.x));
            float h1 = __bfloat162float(__float2bfloat16(v.y));
            float h2 = __bfloat162float(__float2bfloat16(v.z));
            float h3 = __bfloat162float(__float2bfloat16(v.w));
            int sw = swoff(m, k, K);
            *reinterpret_cast<uint2*>(Ahi + sw) =
                make_uint2(bf2_bits(v.x, v.y), bf2_bits(v.z, v.w));
            *reinterpret_cast<uint2*>(Alo + sw) =
                make_uint2(bf2_bits(v.x - h0, v.y - h1), bf2_bits(v.z - h2, v.w - h3));
        }
    }
    // ---- load + split W slice 0 into buffer 0 ----
    {
        const float4* Wg = reinterpret_cast<const float4*>(W);
        #pragma unroll
        for (int p = 0; p < NF4; ++p) {
            int idx = tid + p * 256;
            int n = idx / (K / 4);
            int k = (idx % (K / 4)) * 4;
            float4 v = Wg[idx];
            float h0 = __bfloat162float(__float2bfloat16(v.x));
            float h1 = __bfloat162float(__float2bfloat16(v.y));
            float h2 = __bfloat162float(__float2bfloat16(v.z));
            float h3 = __bfloat162float(__float2bfloat16(v.w));
            int sw = swoff(n, k, K);
            *reinterpret_cast<uint2*>(Wbuf[0][0] + sw) =
                make_uint2(bf2_bits(v.x, v.y), bf2_bits(v.z, v.w));
            *reinterpret_cast<uint2*>(Wbuf[0][1] + sw) =
                make_uint2(bf2_bits(v.x - h0, v.y - h1), bf2_bits(v.z - h2, v.w - h3));
        }
    }
    __syncthreads();

    const int gr = lane >> 2, gc = (lane & 3) * 2;

    for (int nb = 0; nb < 3; ++nb) {
        const char* Wh = Wbuf[nb & 1][0];
        const char* Wl = Wbuf[nb & 1][1];

        // prefetch next W slice (fp32) into registers — LDGs issue before mma
        float4 wpre[NF4];
        if (nb < 2) {
            const float4* Wg = reinterpret_cast<const float4*>(W + (size_t)(nb + 1) * 128 * K);
            #pragma unroll
            for (int p = 0; p < NF4; ++p) wpre[p] = Wg[tid + p * 256];
        }

        // ---- mma phase: fragment-reuse across the 3 split products ----
        float acc[4][4][4];
        #pragma unroll
        for (int i = 0; i < 4; ++i)
            #pragma unroll
            for (int j = 0; j < 4; ++j)
                #pragma unroll
                for (int q = 0; q < 4; ++q) acc[i][j][q] = 0.f;

        #pragma unroll
        for (int kk = 0; kk < K / 16; ++kk) {
            const int kb = kk * 16;
            uint32_t afh[4][4], afl[4][4], bfh[4][2], bfl[4][2];
            #pragma unroll
            for (int mf = 0; mf < 4; ++mf) {
                int row = warp_m * 64 + mf * 16 + (lane & 15);
                int so = swoff(row, kb + (lane >> 4) * 8, K);
                ldsm_x4(afh[mf], smem_u32(Ahi + so));
                ldsm_x4(afl[mf], smem_u32(Alo + so));
            }
            #pragma unroll
            for (int nf = 0; nf < 4; ++nf) {
                int rn = warp_n * 32 + nf * 8 + (lane & 7);
                int so = swoff(rn, kb + ((lane >> 3) & 1) * 8, K);
                ldsm_x2(bfh[nf], smem_u32(Wh + so));
                ldsm_x2(bfl[nf], smem_u32(Wl + so));
            }
            #pragma unroll
            for (int mf = 0; mf < 4; ++mf)
                #pragma unroll
                for (int nf = 0; nf < 4; ++nf) {
                    mma_bf16(acc[mf][nf], afh[mf], bfl[nf]);
                    mma_bf16(acc[mf][nf], afl[mf], bfh[nf]);
                    mma_bf16(acc[mf][nf], afh[mf], bfh[nf]);
                }
        }

        // ---- convert + store prefetched W into the other buffer ----
        if (nb < 2) {
            #pragma unroll
            for (int p = 0; p < NF4; ++p) {
                int idx = tid + p * 256;
                int n = idx / (K / 4);
                int k = (idx % (K / 4)) * 4;
                float4 v = wpre[p];
                float h0 = __bfloat162float(__float2bfloat16(v.x));
                float h1 = __bfloat162float(__float2bfloat16(v.y));
                float h2 = __bfloat162float(__float2bfloat16(v.z));
                float h3 = __bfloat162float(__float2bfloat16(v.w));
                int sw = swoff(n, k, K);
                *reinterpret_cast<uint2*>(Wbuf[(nb + 1) & 1][0] + sw) =
                    make_uint2(bf2_bits(v.x, v.y), bf2_bits(v.z, v.w));
                *reinterpret_cast<uint2*>(Wbuf[(nb + 1) & 1][1] + sw) =
                    make_uint2(bf2_bits(v.x - h0, v.y - h1), bf2_bits(v.z - h2, v.w - h3));
            }
        }

        // ---- epilogue: D + bias -> g_gx slice nb ----
        float bv[4][2];
        #pragma unroll
        for (int nf = 0; nf < 4; ++nf) {
            int col = nb * 128 + warp_n * 32 + nf * 8 + gc;
            bv[nf][0] = bih[col];
            bv[nf][1] = bih[col + 1];
        }
        #pragma unroll
        for (int mf = 0; mf < 4; ++mf) {
            int m0 = mb * 128 + warp_m * 64 + mf * 16 + gr;
            #pragma unroll
            for (int nf = 0; nf < 4; ++nf) {
                int col = nb * 128 + warp_n * 32 + nf * 8 + gc;
                float2 v0 = make_float2(acc[mf][nf][0] + bv[nf][0], acc[mf][nf][1] + bv[nf][1]);
                float2 v1 = make_float2(acc[mf][nf][2] + bv[nf][0], acc[mf][nf][3] + bv[nf][1]);
                *reinterpret_cast<float2*>(g_gx + (size_t)m0 * NG3 + col) = v0;
                *reinterpret_cast<float2*>(g_gx + (size_t)(m0 + 8) * NG3 + col) = v1;
            }
        }

        if (nb < 2) __syncthreads();    // new W buffer visible; old buffer free
    }
}

// ---------------- GRU scan: warp-internal k-split (exact R10/R13 version) ----------------
#define HSEG 40   // padded segment stride (floats): bases hit banks 0/8/16/24
__global__ __launch_bounds__(384, 1)
void gru_scan_kernel(const float* __restrict__ whh, const float* __restrict__ bhh) {
    __shared__ __align__(16) float h0s[4 * HSEG];
    __shared__ __align__(16) float h1s[4 * HSEG];
    __shared__ __align__(16) float accs[2 * NG3];

    const int tid  = threadIdx.x;
    const int wid  = tid >> 5, lane = tid & 31;
    const int kseg = lane & 3;
    const int row0 = wid * 32 + (lane >> 2) * 4;
    const int b0   = blockIdx.x * 2;

    ull wreg[4][16];
    #pragma unroll
    for (int rr = 0; rr < 4; ++rr) {
        const float4* wp = reinterpret_cast<const float4*>(
            whh + (size_t)(row0 + rr) * NH + kseg * 32);
        #pragma unroll
        for (int f = 0; f < 8; ++f) {
            float4 v = wp[f];
            wreg[rr][2 * f]     = pack2(v.x, v.y);
            wreg[rr][2 * f + 1] = pack2(v.z, v.w);
        }
    }
    float bias[4];
    #pragma unroll
    for (int rr = 0; rr < 4; ++rr) bias[rr] = (kseg == 0) ? bhh[row0 + rr] : 0.f;

    const int ub = tid >> 7, uj = tid & 127;
    const int hoff = (uj >> 5) * HSEG + (uj & 31);
    const float* gp   = g_gx   + ((size_t)(b0 + ub) * NT) * NG3 + uj;
    float*       hout = g_hseq + ((size_t)(b0 + ub) * NT) * NH  + uj;
    float gr = 0.f, gz = 0.f, gn = 0.f, hprev = 0.f;
    if (tid < 256) {
        if (ub == 0) h0s[hoff] = 0.f; else h1s[hoff] = 0.f;
        gr = gp[0]; gz = gp[128]; gn = gp[256];
    }
    __syncthreads();

    const ulonglong2* p0 = reinterpret_cast<const ulonglong2*>(h0s + kseg * HSEG);
    const ulonglong2* p1 = reinterpret_cast<const ulonglong2*>(h1s + kseg * HSEG);

    for (int t = 0; t < NT; ++t) {
        float s0[4], s1[4];
        {
            ull a[4] = {0ULL, 0ULL, 0ULL, 0ULL};
            #pragma unroll
            for (int j = 0; j < 8; ++j) {
                ulonglong2 v = p0[j];
                #pragma unroll
                for (int rr = 0; rr < 4; ++rr) {
                    a[rr] = ffma2(wreg[rr][2 * j],     v.x, a[rr]);
                    a[rr] = ffma2(wreg[rr][2 * j + 1], v.y, a[rr]);
                }
            }
            #pragma unroll
            for (int rr = 0; rr < 4; ++rr) {
                float s = f32x2_sum(a[rr]);
                s += __shfl_xor_sync(0xffffffffu, s, 1);
                s += __shfl_xor_sync(0xffffffffu, s, 2);
                s0[rr] = s + bias[rr];
            }
        }
        {
            ull a[4] = {0ULL, 0ULL, 0ULL, 0ULL};
            #pragma unroll
            for (int j = 0; j < 8; ++j) {
                ulonglong2 v = p1[j];
                #pragma unroll
                for (int rr = 0; rr < 4; ++rr) {
                    a[rr] = ffma2(wreg[rr][2 * j],     v.x, a[rr]);
                    a[rr] = ffma2(wreg[rr][2 * j + 1], v.y, a[rr]);
                }
            }
            #pragma unroll
            for (int rr = 0; rr < 4; ++rr) {
                float s = f32x2_sum(a[rr]);
                s += __shfl_xor_sync(0xffffffffu, s, 1);
                s += __shfl_xor_sync(0xffffffffu, s, 2);
                s1[rr] = s + bias[rr];
            }
        }
        if (kseg == 0) {
            *reinterpret_cast<float4*>(accs + row0)       = make_float4(s0[0], s0[1], s0[2], s0[3]);
            *reinterpret_cast<float4*>(accs + NG3 + row0) = make_float4(s1[0], s1[1], s1[2], s1[3]);
        }
        __syncthreads();

        if (tid < 256) {
            const float* ac = accs + ub * NG3;
            float r = 0.5f * tanhapx(0.5f * (gr + ac[uj]))       + 0.5f;
            float z = 0.5f * tanhapx(0.5f * (gz + ac[128 + uj])) + 0.5f;
            float n = tanhapx(gn + r * ac[256 + uj]);
            float hn = n + z * (hprev - n);
            hprev = hn;
            hout[(size_t)t * NH] = hn;
            if (ub == 0) h0s[hoff] = hn; else h1s[hoff] = hn;
            if (t + 1 < NT) {
                const float* g2 = gp + (size_t)(t + 1) * NG3;
                gr = g2[0]; gz = g2[128]; gn = g2[256];
            }
        }
        __syncthreads();
    }
}

// ---------------- final FC ----------------
__global__ void fc_kernel(const float* __restrict__ fcw, const float* __restrict__ fcb,
                          float* __restrict__ out) {
    int b = blockIdx.x;
    int w = threadIdx.x >> 5;
    int lane = threadIdx.x & 31;
    if (w >= 6) return;
    const float* last = g_hseq + ((size_t)b * NT + NT - 1) * NH;
    float s = 0.f;
    #pragma unroll
    for (int k = 0; k < 4; ++k) {
        int j = lane + 32 * k;
        s += last[j] * fcw[w * NH + j];
    }
    #pragma unroll
    for (int o = 16; o; o >>= 1) s += __shfl_down_sync(0xffffffffu, s, o);
    if (lane == 0) out[b * 6 + w] = s + fcb[w];
}

// ---------------- launch ----------------
extern "C" void kernel_launch(void* const* d_in, const int* in_sizes, int n_in,
                              void* d_out, int out_size) {
    const float* x    = (const float*)d_in[0];
    const float* wih0 = (const float*)d_in[1];
    const float* wih1 = (const float*)d_in[2];
    const float* wih2 = (const float*)d_in[3];
    const float* whh  = (const float*)d_in[4];
    const float* bih  = (const float*)d_in[5];
    const float* bhh  = (const float*)d_in[6];
    const float* fcw  = (const float*)d_in[7];
    const float* fcb  = (const float*)d_in[8];
    float* out = (float*)d_out;

    constexpr int SMEM64  = 6 * 128 * 64 * 2;    //  98304
    constexpr int SMEM128 = 6 * 128 * 128 * 2;   // 196608
    cudaFuncSetAttribute(gemm_mma<64>,  cudaFuncAttributeMaxDynamicSharedMemorySize, SMEM64);
    cudaFuncSetAttribute(gemm_mma<128>, cudaFuncAttributeMaxDynamicSharedMemorySize, SMEM128);

    float* g_hseq_ptr = nullptr;
    cudaGetSymbolAddress((void**)&g_hseq_ptr, g_hseq);

    const int ggrid = NB * NT / 128;   // 1024 CTAs

    gemm_mma<64><<<ggrid, 256, SMEM64>>>(x, wih0, bih + 0 * NG3, 0);                  // 1
    gru_scan_kernel<<<NB / 2, 384>>>(whh + 0 * NG3 * NH, bhh + 0 * NG3);              // 2
    gemm_mma<128><<<ggrid, 256, SMEM128>>>(g_hseq_ptr, wih1, bih + 1 * NG3, 0);       // 3
    gru_scan_kernel<<<NB / 2, 384>>>(whh + 1 * NG3 * NH, bhh + 1 * NG3);              // 4
    gemm_mma<128><<<512, 256, SMEM128>>>(g_hseq_ptr, wih2, bih + 2 * NG3, 0);         // 5 (ncu target A)
    gemm_mma<128><<<512, 256, SMEM128>>>(g_hseq_ptr, wih2, bih + 2 * NG3, 512);       // 6 (ncu target B)
    gru_scan_kernel<<<NB / 2, 384>>>(whh + 2 * NG3 * NH, bhh + 2 * NG3);              // 7
    fc_kernel<<<NB, 192>>>(fcw, fcb, out);                                            // 8
}

// round 15
// speedup vs baseline: 1.0503x; 1.0000x over previous
#include <cuda_runtime.h>
#include <cuda_bf16.h>
#include <cstdint>

typedef unsigned long long ull;

#define NB 256
#define NT 512
#define NH 128
#define NG3 384

// ---------------- static scratch ----------------
__device__ float g_gx[(size_t)NB * NT * NG3];
__device__ float g_hseq[(size_t)NB * NT * NH];

// ---------------- helpers ----------------
__device__ __forceinline__ uint32_t smem_u32(const void* p) {
    uint32_t a;
    asm("{ .reg .u64 t; cvta.to.shared.u64 t, %1; cvt.u32.u64 %0, t; }" : "=r"(a) : "l"(p));
    return a;
}
// xor-swizzled byte offset for a [128][K] bf16 tile: 16B chunks permuted by row&7
__device__ __forceinline__ int swoff(int row, int k, int K) {
    return row * K * 2 + ((((k >> 3) ^ (row & 7)) << 4) | ((k & 7) << 1));
}
__device__ __forceinline__ uint32_t bf2_bits(float a, float b) {
    __nv_bfloat162 h = __floats2bfloat162_rn(a, b);
    return *reinterpret_cast<uint32_t*>(&h);
}
__device__ __forceinline__ ull ffma2(ull a, ull b, ull c) {
    ull d;
    asm("fma.rn.f32x2 %0, %1, %2, %3;" : "=l"(d) : "l"(a), "l"(b), "l"(c));
    return d;
}
__device__ __forceinline__ float f32x2_sum(ull a) {
    float lo, hi;
    asm("mov.b64 {%0, %1}, %2;" : "=f"(lo), "=f"(hi) : "l"(a));
    return lo + hi;
}
__device__ __forceinline__ ull pack2(float lo, float hi) {
    ull u;
    asm("mov.b64 %0, {%1, %2};" : "=l"(u) : "f"(lo), "f"(hi));
    return u;
}
__device__ __forceinline__ float tanhapx(float x) {
    float y;
    asm("tanh.approx.f32 %0, %1;" : "=f"(y) : "f"(x));
    return y;
}

__device__ __forceinline__ void ldsm_x4(uint32_t* r, uint32_t addr) {
    asm volatile("ldmatrix.sync.aligned.m8n8.x4.shared.b16 {%0,%1,%2,%3}, [%4];"
                 : "=r"(r[0]), "=r"(r[1]), "=r"(r[2]), "=r"(r[3]) : "r"(addr));
}
__device__ __forceinline__ void ldsm_x2(uint32_t* r, uint32_t addr) {
    asm volatile("ldmatrix.sync.aligned.m8n8.x2.shared.b16 {%0,%1}, [%2];"
                 : "=r"(r[0]), "=r"(r[1]) : "r"(addr));
}
__device__ __forceinline__ void mma_bf16(float* c, const uint32_t* a, const uint32_t* b) {
    asm volatile(
        "mma.sync.aligned.m16n8k16.row.col.f32.bf16.bf16.f32 "
        "{%0,%1,%2,%3}, {%4,%5,%6,%7}, {%8,%9}, {%0,%1,%2,%3};"
        : "+f"(c[0]), "+f"(c[1]), "+f"(c[2]), "+f"(c[3])
        : "r"(a[0]), "r"(a[1]), "r"(a[2]), "r"(a[3]), "r"(b[0]), "r"(b[1]));
}

// ---------------- gx GEMM: g_gx[m,384] = A[m,K] @ W^T + b_ih ----------------
// A-resident + double-buffered W + register prefetch + fragment-reuse mma loop.
// smem = A(hi,lo) + W(hi,lo) x 2 buffers = 6 tiles.
template <int K>
__global__ __launch_bounds__(256, 1)
void gemm_mma(const float* __restrict__ A, const float* __restrict__ W,
              const float* __restrict__ bih, int mb_off) {
    extern __shared__ char sm[];
    constexpr int TILE = 128 * K * 2;
    constexpr int NF4  = (128 * (K / 4)) / 256;    // float4 per thread per W tile
    char* Ahi = sm;
    char* Alo = Ahi + TILE;
    char* Wbuf[2][2] = { { Alo + TILE,            Alo + 2 * TILE },
                         { Alo + 3 * TILE,        Alo + 4 * TILE } };  // [buf][hi/lo]

    const int tid = threadIdx.x;
    const int wid = tid >> 5, lane = tid & 31;
    const int mb = blockIdx.x + mb_off;
    const int warp_m = wid >> 2;        // 0..1  (64 rows each)
    const int warp_n = wid & 3;         // 0..3  (32 cols each)

    // ---- load + split A tile (once) ----
    {
        const float4* Ag = reinterpret_cast<const float4*>(A + (size_t)mb * 128 * K);
        #pragma unroll
        for (int p = 0; p < NF4; ++p) {
            int idx = tid + p * 256;
            int m = idx / (K / 4);
            int k = (idx % (K / 4)) * 4;
            float4 v = Ag[idx];
            float h0 = __bfloat162float(__float2bfloat16(v.x));
            float h1 = __bfloat162float(__float2bfloat16(v.y));
            float h2 = __bfloat162float(__float2bfloat16(v.z));
            float h3 = __bfloat162float(__float2bfloat16(v.w));
            int sw = swoff(m, k, K);
            *reinterpret_cast<uint2*>(Ahi + sw) =
                make_uint2(bf2_bits(v.x, v.y), bf2_bits(v.z, v.w));
            *reinterpret_cast<uint2*>(Alo + sw) =
                make_uint2(bf2_bits(v.x - h0, v.y - h1), bf2_bits(v.z - h2, v.w - h3));
        }
    }
    // ---- load + split W slice 0 into buffer 0 ----
    {
        const float4* Wg = reinterpret_cast<const float4*>(W);
        #pragma unroll
        for (int p = 0; p < NF4; ++p) {
            int idx = tid + p * 256;
            int n = idx / (K / 4);
            int k = (idx % (K / 4)) * 4;
            float4 v = Wg[idx];
            float h0 = __bfloat162float(__float2bfloat16(v.x));
            float h1 = __bfloat162float(__float2bfloat16(v.y));
            float h2 = __bfloat162float(__float2bfloat16(v.z));
            float h3 = __bfloat162float(__float2bfloat16(v.w));
            int sw = swoff(n, k, K);
            *reinterpret_cast<uint2*>(Wbuf[0][0] + sw) =
                make_uint2(bf2_bits(v.x, v.y), bf2_bits(v.z, v.w));
            *reinterpret_cast<uint2*>(Wbuf[0][1] + sw) =
                make_uint2(bf2_bits(v.x - h0, v.y - h1), bf2_bits(v.z - h2, v.w - h3));
        }
    }
    __syncthreads();

    const int gr = lane >> 2, gc = (lane & 3) * 2;

    for (int nb = 0; nb < 3; ++nb) {
        const char* Wh = Wbuf[nb & 1][0];
        const char* Wl = Wbuf[nb & 1][1];

        // prefetch next W slice (fp32) into registers — LDGs issue before mma
        float4 wpre[NF4];
        if (nb < 2) {
            const float4* Wg = reinterpret_cast<const float4*>(W + (size_t)(nb + 1) * 128 * K);
            #pragma unroll
            for (int p = 0; p < NF4; ++p) wpre[p] = Wg[tid + p * 256];
        }

        // ---- mma phase: fragment-reuse across the 3 split products ----
        float acc[4][4][4];
        #pragma unroll
        for (int i = 0; i < 4; ++i)
            #pragma unroll
            for (int j = 0; j < 4; ++j)
                #pragma unroll
                for (int q = 0; q < 4; ++q) acc[i][j][q] = 0.f;

        #pragma unroll
        for (int kk = 0; kk < K / 16; ++kk) {
            const int kb = kk * 16;
            uint32_t afh[4][4], afl[4][4], bfh[4][2], bfl[4][2];
            #pragma unroll
            for (int mf = 0; mf < 4; ++mf) {
                int row = warp_m * 64 + mf * 16 + (lane & 15);
                int so = swoff(row, kb + (lane >> 4) * 8, K);
                ldsm_x4(afh[mf], smem_u32(Ahi + so));
                ldsm_x4(afl[mf], smem_u32(Alo + so));
            }
            #pragma unroll
            for (int nf = 0; nf < 4; ++nf) {
                int rn = warp_n * 32 + nf * 8 + (lane & 7);
                int so = swoff(rn, kb + ((lane >> 3) & 1) * 8, K);
                ldsm_x2(bfh[nf], smem_u32(Wh + so));
                ldsm_x2(bfl[nf], smem_u32(Wl + so));
            }
            #pragma unroll
            for (int mf = 0; mf < 4; ++mf)
                #pragma unroll
                for (int nf = 0; nf < 4; ++nf) {
                    mma_bf16(acc[mf][nf], afh[mf], bfl[nf]);
                    mma_bf16(acc[mf][nf], afl[mf], bfh[nf]);
                    mma_bf16(acc[mf][nf], afh[mf], bfh[nf]);
                }
        }

        // ---- convert + store prefetched W into the other buffer ----
        if (nb < 2) {
            #pragma unroll
            for (int p = 0; p < NF4; ++p) {
                int idx = tid + p * 256;
                int n = idx / (K / 4);
                int k = (idx % (K / 4)) * 4;
                float4 v = wpre[p];
                float h0 = __bfloat162float(__float2bfloat16(v.x));
                float h1 = __bfloat162float(__float2bfloat16(v.y));
                float h2 = __bfloat162float(__float2bfloat16(v.z));
                float h3 = __bfloat162float(__float2bfloat16(v.w));
                int sw = swoff(n, k, K);
                *reinterpret_cast<uint2*>(Wbuf[(nb + 1) & 1][0] + sw) =
                    make_uint2(bf2_bits(v.x, v.y), bf2_bits(v.z, v.w));
                *reinterpret_cast<uint2*>(Wbuf[(nb + 1) & 1][1] + sw) =
                    make_uint2(bf2_bits(v.x - h0, v.y - h1), bf2_bits(v.z - h2, v.w - h3));
            }
        }

        // ---- epilogue: D + bias -> g_gx slice nb ----
        float bv[4][2];
        #pragma unroll
        for (int nf = 0; nf < 4; ++nf) {
            int col = nb * 128 + warp_n * 32 + nf * 8 + gc;
            bv[nf][0] = bih[col];
            bv[nf][1] = bih[col + 1];
        }
        #pragma unroll
        for (int mf = 0; mf < 4; ++mf) {
            int m0 = mb * 128 + warp_m * 64 + mf * 16 + gr;
            #pragma unroll
            for (int nf = 0; nf < 4; ++nf) {
                int col = nb * 128 + warp_n * 32 + nf * 8 + gc;
                float2 v0 = make_float2(acc[mf][nf][0] + bv[nf][0], acc[mf][nf][1] + bv[nf][1]);
                float2 v1 = make_float2(acc[mf][nf][2] + bv[nf][0], acc[mf][nf][3] + bv[nf][1]);
                *reinterpret_cast<float2*>(g_gx + (size_t)m0 * NG3 + col) = v0;
                *reinterpret_cast<float2*>(g_gx + (size_t)(m0 + 8) * NG3 + col) = v1;
            }
        }

        if (nb < 2) __syncthreads();    // new W buffer visible; old buffer free
    }
}

// ---------------- GRU scan: warp-internal k-split (exact R10/R13 version) ----------------
#define HSEG 40   // padded segment stride (floats): bases hit banks 0/8/16/24
__global__ __launch_bounds__(384, 1)
void gru_scan_kernel(const float* __restrict__ whh, const float* __restrict__ bhh) {
    __shared__ __align__(16) float h0s[4 * HSEG];
    __shared__ __align__(16) float h1s[4 * HSEG];
    __shared__ __align__(16) float accs[2 * NG3];

    const int tid  = threadIdx.x;
    const int wid  = tid >> 5, lane = tid & 31;
    const int kseg = lane & 3;
    const int row0 = wid * 32 + (lane >> 2) * 4;
    const int b0   = blockIdx.x * 2;

    ull wreg[4][16];
    #pragma unroll
    for (int rr = 0; rr < 4; ++rr) {
        const float4* wp = reinterpret_cast<const float4*>(
            whh + (size_t)(row0 + rr) * NH + kseg * 32);
        #pragma unroll
        for (int f = 0; f < 8; ++f) {
            float4 v = wp[f];
            wreg[rr][2 * f]     = pack2(v.x, v.y);
            wreg[rr][2 * f + 1] = pack2(v.z, v.w);
        }
    }
    float bias[4];
    #pragma unroll
    for (int rr = 0; rr < 4; ++rr) bias[rr] = (kseg == 0) ? bhh[row0 + rr] : 0.f;

    const int ub = tid >> 7, uj = tid & 127;
    const int hoff = (uj >> 5) * HSEG + (uj & 31);
    const float* gp   = g_gx   + ((size_t)(b0 + ub) * NT) * NG3 + uj;
    float*       hout = g_hseq + ((size_t)(b0 + ub) * NT) * NH  + uj;
    float gr = 0.f, gz = 0.f, gn = 0.f, hprev = 0.f;
    if (tid < 256) {
        if (ub == 0) h0s[hoff] = 0.f; else h1s[hoff] = 0.f;
        gr = gp[0]; gz = gp[128]; gn = gp[256];
    }
    __syncthreads();

    const ulonglong2* p0 = reinterpret_cast<const ulonglong2*>(h0s + kseg * HSEG);
    const ulonglong2* p1 = reinterpret_cast<const ulonglong2*>(h1s + kseg * HSEG);

    for (int t = 0; t < NT; ++t) {
        float s0[4], s1[4];
        {
            ull a[4] = {0ULL, 0ULL, 0ULL, 0ULL};
            #pragma unroll
            for (int j = 0; j < 8; ++j) {
                ulonglong2 v = p0[j];
                #pragma unroll
                for (int rr = 0; rr < 4; ++rr) {
                    a[rr] = ffma2(wreg[rr][2 * j],     v.x, a[rr]);
                    a[rr] = ffma2(wreg[rr][2 * j + 1], v.y, a[rr]);
                }
            }
            #pragma unroll
            for (int rr = 0; rr < 4; ++rr) {
                float s = f32x2_sum(a[rr]);
                s += __shfl_xor_sync(0xffffffffu, s, 1);
                s += __shfl_xor_sync(0xffffffffu, s, 2);
                s0[rr] = s + bias[rr];
            }
        }
        {
            ull a[4] = {0ULL, 0ULL, 0ULL, 0ULL};
            #pragma unroll
            for (int j = 0; j < 8; ++j) {
                ulonglong2 v = p1[j];
                #pragma unroll
                for (int rr = 0; rr < 4; ++rr) {
                    a[rr] = ffma2(wreg[rr][2 * j],     v.x, a[rr]);
                    a[rr] = ffma2(wreg[rr][2 * j + 1], v.y, a[rr]);
                }
            }
            #pragma unroll
            for (int rr = 0; rr < 4; ++rr) {
                float s = f32x2_sum(a[rr]);
                s += __shfl_xor_sync(0xffffffffu, s, 1);
                s += __shfl_xor_sync(0xffffffffu, s, 2);
                s1[rr] = s + bias[rr];
            }
        }
        if (kseg == 0) {
            *reinterpret_cast<float4*>(accs + row0)       = make_float4(s0[0], s0[1], s0[2], s0[3]);
            *reinterpret_cast<float4*>(accs + NG3 + row0) = make_float4(s1[0], s1[1], s1[2], s1[3]);
        }
        __syncthreads();

        if (tid < 256) {
            const float* ac = accs + ub * NG3;
            float r = 0.5f * tanhapx(0.5f * (gr + ac[uj]))       + 0.5f;
            float z = 0.5f * tanhapx(0.5f * (gz + ac[128 + uj])) + 0.5f;
            float n = tanhapx(gn + r * ac[256 + uj]);
            float hn = n + z * (hprev - n);
            hprev = hn;
            hout[(size_t)t * NH] = hn;
            if (ub == 0) h0s[hoff] = hn; else h1s[hoff] = hn;
            if (t + 1 < NT) {
                const float* g2 = gp + (size_t)(t + 1) * NG3;
                gr = g2[0]; gz = g2[128]; gn = g2[256];
            }
        }
        __syncthreads();
    }
}

// ---------------- final FC ----------------
__global__ void fc_kernel(const float* __restrict__ fcw, const float* __restrict__ fcb,
                          float* __restrict__ out) {
    int b = blockIdx.x;
    int w = threadIdx.x >> 5;
    int lane = threadIdx.x & 31;
    if (w >= 6) return;
    const float* last = g_hseq + ((size_t)b * NT + NT - 1) * NH;
    float s = 0.f;
    #pragma unroll
    for (int k = 0; k < 4; ++k) {
        int j = lane + 32 * k;
        s += last[j] * fcw[w * NH + j];
    }
    #pragma unroll
    for (int o = 16; o; o >>= 1) s += __shfl_down_sync(0xffffffffu, s, o);
    if (lane == 0) out[b * 6 + w] = s + fcb[w];
}

// ---------------- launch ----------------
extern "C" void kernel_launch(void* const* d_in, const int* in_sizes, int n_in,
                              void* d_out, int out_size) {
    const float* x    = (const float*)d_in[0];
    const float* wih0 = (const float*)d_in[1];
    const float* wih1 = (const float*)d_in[2];
    const float* wih2 = (const float*)d_in[3];
    const float* whh  = (const float*)d_in[4];
    const float* bih  = (const float*)d_in[5];
    const float* bhh  = (const float*)d_in[6];
    const float* fcw  = (const float*)d_in[7];
    const float* fcb  = (const float*)d_in[8];
    float* out = (float*)d_out;

    constexpr int SMEM64  = 6 * 128 * 64 * 2;    //  98304
    constexpr int SMEM128 = 6 * 128 * 128 * 2;   // 196608
    cudaFuncSetAttribute(gemm_mma<64>,  cudaFuncAttributeMaxDynamicSharedMemorySize, SMEM64);
    cudaFuncSetAttribute(gemm_mma<128>, cudaFuncAttributeMaxDynamicSharedMemorySize, SMEM128);

    float* g_hseq_ptr = nullptr;
    cudaGetSymbolAddress((void**)&g_hseq_ptr, g_hseq);

    const int ggrid = NB * NT / 128;   // 1024 CTAs

    gemm_mma<64><<<ggrid, 256, SMEM64>>>(x, wih0, bih + 0 * NG3, 0);                  // 1
    gru_scan_kernel<<<NB / 2, 384>>>(whh + 0 * NG3 * NH, bhh + 0 * NG3);              // 2
    gemm_mma<128><<<ggrid, 256, SMEM128>>>(g_hseq_ptr, wih1, bih + 1 * NG3, 0);       // 3
    gru_scan_kernel<<<NB / 2, 384>>>(whh + 1 * NG3 * NH, bhh + 1 * NG3);              // 4
    gemm_mma<128><<<512, 256, SMEM128>>>(g_hseq_ptr, wih2, bih + 2 * NG3, 0);         // 5 (ncu target A)
    gemm_mma<128><<<512, 256, SMEM128>>>(g_hseq_ptr, wih2, bih + 2 * NG3, 512);       // 6 (ncu target B)
    gru_scan_kernel<<<NB / 2, 384>>>(whh + 2 * NG3 * NH, bhh + 2 * NG3);              // 7
    fc_kernel<<<NB, 192>>>(fcw, fcb, out);                                            // 8
}

// round 16
// speedup vs baseline: 1.0626x; 1.0117x over previous
#include <cuda_runtime.h>
#include <cuda_bf16.h>
#include <cstdint>

typedef unsigned long long ull;

#define NB 256
#define NT 512
#define NH 128
#define NG3 384

// ---------------- static scratch ----------------
__device__ float g_gx[(size_t)NB * NT * NG3];
__device__ float g_hseq[(size_t)NB * NT * NH];

// ---------------- helpers ----------------
__device__ __forceinline__ uint32_t smem_u32(const void* p) {
    uint32_t a;
    asm("{ .reg .u64 t; cvta.to.shared.u64 t, %1; cvt.u32.u64 %0, t; }" : "=r"(a) : "l"(p));
    return a;
}
__device__ __forceinline__ int swoff(int row, int k, int K) {
    return row * K * 2 + ((((k >> 3) ^ (row & 7)) << 4) | ((k & 7) << 1));
}
__device__ __forceinline__ uint32_t bf2_bits(float a, float b) {
    __nv_bfloat162 h = __floats2bfloat162_rn(a, b);
    return *reinterpret_cast<uint32_t*>(&h);
}
__device__ __forceinline__ ull ffma2(ull a, ull b, ull c) {
    ull d;
    asm("fma.rn.f32x2 %0, %1, %2, %3;" : "=l"(d) : "l"(a), "l"(b), "l"(c));
    return d;
}
__device__ __forceinline__ float f32x2_sum(ull a) {
    float lo, hi;
    asm("mov.b64 {%0, %1}, %2;" : "=f"(lo), "=f"(hi) : "l"(a));
    return lo + hi;
}
__device__ __forceinline__ ull pack2(float lo, float hi) {
    ull u;
    asm("mov.b64 %0, {%1, %2};" : "=l"(u) : "f"(lo), "f"(hi));
    return u;
}
__device__ __forceinline__ float tanhapx(float x) {
    float y;
    asm("tanh.approx.f32 %0, %1;" : "=f"(y) : "f"(x));
    return y;
}

__device__ __forceinline__ void ldsm_x4(uint32_t* r, uint32_t addr) {
    asm volatile("ldmatrix.sync.aligned.m8n8.x4.shared.b16 {%0,%1,%2,%3}, [%4];"
                 : "=r"(r[0]), "=r"(r[1]), "=r"(r[2]), "=r"(r[3]) : "r"(addr));
}
__device__ __forceinline__ void ldsm_x2(uint32_t* r, uint32_t addr) {
    asm volatile("ldmatrix.sync.aligned.m8n8.x2.shared.b16 {%0,%1}, [%2];"
                 : "=r"(r[0]), "=r"(r[1]) : "r"(addr));
}
__device__ __forceinline__ void mma_bf16(float* c, const uint32_t* a, const uint32_t* b) {
    asm volatile(
        "mma.sync.aligned.m16n8k16.row.col.f32.bf16.bf16.f32 "
        "{%0,%1,%2,%3}, {%4,%5,%6,%7}, {%8,%9}, {%0,%1,%2,%3};"
        : "+f"(c[0]), "+f"(c[1]), "+f"(c[2]), "+f"(c[3])
        : "r"(a[0]), "r"(a[1]), "r"(a[2]), "r"(a[3]), "r"(b[0]), "r"(b[1]));
}

// ---------------- gx GEMM (exact R15 best: A-resident + W double-buffer + frag reuse) ----------------
template <int K>
__global__ __launch_bounds__(256, 1)
void gemm_mma(const float* __restrict__ A, const float* __restrict__ W,
              const float* __restrict__ bih, int mb_off) {
    extern __shared__ char sm[];
    constexpr int TILE = 128 * K * 2;
    constexpr int NF4  = (128 * (K / 4)) / 256;
    char* Ahi = sm;
    char* Alo = Ahi + TILE;
    char* Wbuf[2][2] = { { Alo + TILE,     Alo + 2 * TILE },
                         { Alo + 3 * TILE, Alo + 4 * TILE } };

    const int tid = threadIdx.x;
    const int wid = tid >> 5, lane = tid & 31;
    const int mb = blockIdx.x + mb_off;
    const int warp_m = wid >> 2;
    const int warp_n = wid & 3;

    {
        const float4* Ag = reinterpret_cast<const float4*>(A + (size_t)mb * 128 * K);
        #pragma unroll
        for (int p = 0; p < NF4; ++p) {
            int idx = tid + p * 256;
            int m = idx / (K / 4);
            int k = (idx % (K / 4)) * 4;
            float4 v = Ag[idx];
            float h0 = __bfloat162float(__float2bfloat16(v.x));
            float h1 = __bfloat162float(__float2bfloat16(v.y));
            float h2 = __bfloat162float(__float2bfloat16(v.z));
            float h3 = __bfloat162float(__float2bfloat16(v.w));
            int sw = swoff(m, k, K);
            *reinterpret_cast<uint2*>(Ahi + sw) =
                make_uint2(bf2_bits(v.x, v.y), bf2_bits(v.z, v.w));
            *reinterpret_cast<uint2*>(Alo + sw) =
                make_uint2(bf2_bits(v.x - h0, v.y - h1), bf2_bits(v.z - h2, v.w - h3));
        }
    }
    {
        const float4* Wg = reinterpret_cast<const float4*>(W);
        #pragma unroll
        for (int p = 0; p < NF4; ++p) {
            int idx = tid + p * 256;
            int n = idx / (K / 4);
            int k = (idx % (K / 4)) * 4;
            float4 v = Wg[idx];
            float h0 = __bfloat162float(__float2bfloat16(v.x));
            float h1 = __bfloat162float(__float2bfloat16(v.y));
            float h2 = __bfloat162float(__float2bfloat16(v.z));
            float h3 = __bfloat162float(__float2bfloat16(v.w));
            int sw = swoff(n, k, K);
            *reinterpret_cast<uint2*>(Wbuf[0][0] + sw) =
                make_uint2(bf2_bits(v.x, v.y), bf2_bits(v.z, v.w));
            *reinterpret_cast<uint2*>(Wbuf[0][1] + sw) =
                make_uint2(bf2_bits(v.x - h0, v.y - h1), bf2_bits(v.z - h2, v.w - h3));
        }
    }
    __syncthreads();

    const int gr = lane >> 2, gc = (lane & 3) * 2;

    for (int nb = 0; nb < 3; ++nb) {
        const char* Wh = Wbuf[nb & 1][0];
        const char* Wl = Wbuf[nb & 1][1];

        float4 wpre[NF4];
        if (nb < 2) {
            const float4* Wg = reinterpret_cast<const float4*>(W + (size_t)(nb + 1) * 128 * K);
            #pragma unroll
            for (int p = 0; p < NF4; ++p) wpre[p] = Wg[tid + p * 256];
        }

        float acc[4][4][4];
        #pragma unroll
        for (int i = 0; i < 4; ++i)
            #pragma unroll
            for (int j = 0; j < 4; ++j)
                #pragma unroll
                for (int q = 0; q < 4; ++q) acc[i][j][q] = 0.f;

        #pragma unroll
        for (int kk = 0; kk < K / 16; ++kk) {
            const int kb = kk * 16;
            uint32_t afh[4][4], afl[4][4], bfh[4][2], bfl[4][2];
            #pragma unroll
            for (int mf = 0; mf < 4; ++mf) {
                int row = warp_m * 64 + mf * 16 + (lane & 15);
                int so = swoff(row, kb + (lane >> 4) * 8, K);
                ldsm_x4(afh[mf], smem_u32(Ahi + so));
                ldsm_x4(afl[mf], smem_u32(Alo + so));
            }
            #pragma unroll
            for (int nf = 0; nf < 4; ++nf) {
                int rn = warp_n * 32 + nf * 8 + (lane & 7);
                int so = swoff(rn, kb + ((lane >> 3) & 1) * 8, K);
                ldsm_x2(bfh[nf], smem_u32(Wh + so));
                ldsm_x2(bfl[nf], smem_u32(Wl + so));
            }
            #pragma unroll
            for (int mf = 0; mf < 4; ++mf)
                #pragma unroll
                for (int nf = 0; nf < 4; ++nf) {
                    mma_bf16(acc[mf][nf], afh[mf], bfl[nf]);
                    mma_bf16(acc[mf][nf], afl[mf], bfh[nf]);
                    mma_bf16(acc[mf][nf], afh[mf], bfh[nf]);
                }
        }

        if (nb < 2) {
            #pragma unroll
            for (int p = 0; p < NF4; ++p) {
                int idx = tid + p * 256;
                int n = idx / (K / 4);
                int k = (idx % (K / 4)) * 4;
                float4 v = wpre[p];
                float h0 = __bfloat162float(__float2bfloat16(v.x));
                float h1 = __bfloat162float(__float2bfloat16(v.y));
                float h2 = __bfloat162float(__float2bfloat16(v.z));
                float h3 = __bfloat162float(__float2bfloat16(v.w));
                int sw = swoff(n, k, K);
                *reinterpret_cast<uint2*>(Wbuf[(nb + 1) & 1][0] + sw) =
                    make_uint2(bf2_bits(v.x, v.y), bf2_bits(v.z, v.w));
                *reinterpret_cast<uint2*>(Wbuf[(nb + 1) & 1][1] + sw) =
                    make_uint2(bf2_bits(v.x - h0, v.y - h1), bf2_bits(v.z - h2, v.w - h3));
            }
        }

        float bv[4][2];
        #pragma unroll
        for (int nf = 0; nf < 4; ++nf) {
            int col = nb * 128 + warp_n * 32 + nf * 8 + gc;
            bv[nf][0] = bih[col];
            bv[nf][1] = bih[col + 1];
        }
        #pragma unroll
        for (int mf = 0; mf < 4; ++mf) {
            int m0 = mb * 128 + warp_m * 64 + mf * 16 + gr;
            #pragma unroll
            for (int nf = 0; nf < 4; ++nf) {
                int col = nb * 128 + warp_n * 32 + nf * 8 + gc;
                float2 v0 = make_float2(acc[mf][nf][0] + bv[nf][0], acc[mf][nf][1] + bv[nf][1]);
                float2 v1 = make_float2(acc[mf][nf][2] + bv[nf][0], acc[mf][nf][3] + bv[nf][1]);
                *reinterpret_cast<float2*>(g_gx + (size_t)m0 * NG3 + col) = v0;
                *reinterpret_cast<float2*>(g_gx + (size_t)(m0 + 8) * NG3 + col) = v1;
            }
        }

        if (nb < 2) __syncthreads();
    }
}

// ---------------- GRU scan v5: fused gates, ONE barrier/step ----------------
// 256 threads: thread = (unit j = tid>>1, khalf ks = tid&1). Owns W rows
// {j, j+128, j+256} x 64-k-half in registers (192 regs). Computes r/z/n partials
// for both batches, shfl.xor(1) merges k-halves, ks==0 lane computes gates
// locally and writes h to the parity-alternating smem buffer. One BAR per step.
__global__ __launch_bounds__(256, 1)
void gru_scan_kernel(const float* __restrict__ whh, const float* __restrict__ bhh) {
    // h buffers: [parity][batch][kseg*68 + i], padded so ks=1 base shifts banks
    __shared__ __align__(16) float hs[2 * 2 * 136];

    const int tid = threadIdx.x;
    const int ks  = tid & 1;
    const int j   = tid >> 1;
    const int b0  = blockIdx.x * 2;

    // W: rows j, j+128, j+256; k in [ks*64, ks*64+64) as 32 f32x2 each
    ull wreg[3][32];
    #pragma unroll
    for (int r = 0; r < 3; ++r) {
        const float4* wp = reinterpret_cast<const float4*>(
            whh + (size_t)(r * 128 + j) * NH + ks * 64);
        #pragma unroll
        for (int f = 0; f < 16; ++f) {
            float4 v = wp[f];
            wreg[r][2 * f]     = pack2(v.x, v.y);
            wreg[r][2 * f + 1] = pack2(v.z, v.w);
        }
    }

    float br = 0.f, bz = 0.f, bn = 0.f;
    float gxr[2], gxz[2], gxn[2], hprev[2];
    const float* gp0 = g_gx + ((size_t)(b0 + 0) * NT) * NG3 + j;
    const float* gp1 = g_gx + ((size_t)(b0 + 1) * NT) * NG3 + j;
    float* ho0 = g_hseq + ((size_t)(b0 + 0) * NT) * NH + j;
    float* ho1 = g_hseq + ((size_t)(b0 + 1) * NT) * NH + j;
    hprev[0] = hprev[1] = 0.f;
    gxr[0] = gxr[1] = gxz[0] = gxz[1] = gxn[0] = gxn[1] = 0.f;

    if (ks == 0) {
        br = bhh[j]; bz = bhh[128 + j]; bn = bhh[256 + j];
        gxr[0] = gp0[0]; gxz[0] = gp0[128]; gxn[0] = gp0[256];
        gxr[1] = gp1[0]; gxz[1] = gp1[128]; gxn[1] = gp1[256];
        // init h(0) = 0 in parity-0 buffers (both batches, this unit's slot)
        hs[(0 * 2 + 0) * 136 + (j >> 6) * 68 + (j & 63)] = 0.f;
        hs[(0 * 2 + 1) * 136 + (j >> 6) * 68 + (j & 63)] = 0.f;
    }
    __syncthreads();

    for (int t = 0; t < NT; ++t) {
        const int par = t & 1;
        const ulonglong2* p0 = reinterpret_cast<const ulonglong2*>(
            hs + (par * 2 + 0) * 136 + ks * 68);
        const ulonglong2* p1 = reinterpret_cast<const ulonglong2*>(
            hs + (par * 2 + 1) * 136 + ks * 68);

        ull a[3][2];
        #pragma unroll
        for (int r = 0; r < 3; ++r) { a[r][0] = 0ULL; a[r][1] = 0ULL; }

        #pragma unroll
        for (int q = 0; q < 16; ++q) {
            ulonglong2 v0 = p0[q];
            ulonglong2 v1 = p1[q];
            #pragma unroll
            for (int r = 0; r < 3; ++r) {
                a[r][0] = ffma2(wreg[r][2 * q],     v0.x, a[r][0]);
                a[r][0] = ffma2(wreg[r][2 * q + 1], v0.y, a[r][0]);
                a[r][1] = ffma2(wreg[r][2 * q],     v1.x, a[r][1]);
                a[r][1] = ffma2(wreg[r][2 * q + 1], v1.y, a[r][1]);
            }
        }

        float s[3][2];
        #pragma unroll
        for (int r = 0; r < 3; ++r)
            #pragma unroll
            for (int b = 0; b < 2; ++b) {
                float v = f32x2_sum(a[r][b]);
                s[r][b] = v + __shfl_xor_sync(0xffffffffu, v, 1);
            }

        if (ks == 0) {
            const int np = (t + 1) & 1;
            const int hsl = (j >> 6) * 68 + (j & 63);
            #pragma unroll
            for (int b = 0; b < 2; ++b) {
                float rr = 0.5f * tanhapx(0.5f * (gxr[b] + s[0][b] + br)) + 0.5f;
                float zz = 0.5f * tanhapx(0.5f * (gxz[b] + s[1][b] + bz)) + 0.5f;
                float nn = tanhapx(gxn[b] + rr * (s[2][b] + bn));
                float hn = nn + zz * (hprev[b] - nn);
                hprev[b] = hn;
                hs[(np * 2 + b) * 136 + hsl] = hn;
                if (b == 0) ho0[(size_t)t * NH] = hn;
                else        ho1[(size_t)t * NH] = hn;
            }
            if (t + 1 < NT) {
                const float* g0 = gp0 + (size_t)(t + 1) * NG3;
                const float* g1 = gp1 + (size_t)(t + 1) * NG3;
                gxr[0] = g0[0]; gxz[0] = g0[128]; gxn[0] = g0[256];
                gxr[1] = g1[0]; gxz[1] = g1[128]; gxn[1] = g1[256];
            }
        }
        __syncthreads();
    }
}

// ---------------- final FC ----------------
__global__ void fc_kernel(const float* __restrict__ fcw, const float* __restrict__ fcb,
                          float* __restrict__ out) {
    int b = blockIdx.x;
    int w = threadIdx.x >> 5;
    int lane = threadIdx.x & 31;
    if (w >= 6) return;
    const float* last = g_hseq + ((size_t)b * NT + NT - 1) * NH;
    float s = 0.f;
    #pragma unroll
    for (int k = 0; k < 4; ++k) {
        int j = lane + 32 * k;
        s += last[j] * fcw[w * NH + j];
    }
    #pragma unroll
    for (int o = 16; o; o >>= 1) s += __shfl_down_sync(0xffffffffu, s, o);
    if (lane == 0) out[b * 6 + w] = s + fcb[w];
}

// ---------------- launch ----------------
extern "C" void kernel_launch(void* const* d_in, const int* in_sizes, int n_in,
                              void* d_out, int out_size) {
    const float* x    = (const float*)d_in[0];
    const float* wih0 = (const float*)d_in[1];
    const float* wih1 = (const float*)d_in[2];
    const float* wih2 = (const float*)d_in[3];
    const float* whh  = (const float*)d_in[4];
    const float* bih  = (const float*)d_in[5];
    const float* bhh  = (const float*)d_in[6];
    const float* fcw  = (const float*)d_in[7];
    const float* fcb  = (const float*)d_in[8];
    float* out = (float*)d_out;

    constexpr int SMEM64  = 6 * 128 * 64 * 2;    //  98304
    constexpr int SMEM128 = 6 * 128 * 128 * 2;   // 196608
    cudaFuncSetAttribute(gemm_mma<64>,  cudaFuncAttributeMaxDynamicSharedMemorySize, SMEM64);
    cudaFuncSetAttribute(gemm_mma<128>, cudaFuncAttributeMaxDynamicSharedMemorySize, SMEM128);

    float* g_hseq_ptr = nullptr;
    cudaGetSymbolAddress((void**)&g_hseq_ptr, g_hseq);

    const int ggrid = NB * NT / 128;   // 1024 CTAs

    gemm_mma<64><<<ggrid, 256, SMEM64>>>(x, wih0, bih + 0 * NG3, 0);                  // 1
    gru_scan_kernel<<<NB / 2, 256>>>(whh + 0 * NG3 * NH, bhh + 0 * NG3);              // 2
    gemm_mma<128><<<ggrid, 256, SMEM128>>>(g_hseq_ptr, wih1, bih + 1 * NG3, 0);       // 3
    gru_scan_kernel<<<NB / 2, 256>>>(whh + 1 * NG3 * NH, bhh + 1 * NG3);              // 4
    gemm_mma<128><<<512, 256, SMEM128>>>(g_hseq_ptr, wih2, bih + 2 * NG3, 0);         // 5
    gemm_mma<128><<<512, 256, SMEM128>>>(g_hseq_ptr, wih2, bih + 2 * NG3, 512);       // 6
    gru_scan_kernel<<<NB / 2, 256>>>(whh + 2 * NG3 * NH, bhh + 2 * NG3);              // 7
    fc_kernel<<<NB, 192>>>(fcw, fcb, out);                                            // 8
}

// round 17
// speedup vs baseline: 1.0646x; 1.0018x over previous
#include <cuda_runtime.h>
#include <cuda_bf16.h>
#include <cstdint>

typedef unsigned long long ull;

#define NB 256
#define NT 512
#define NH 128
#define NG3 384

// ---------------- static scratch ----------------
__device__ float g_gx[(size_t)NB * NT * NG3];
__device__ float g_hseq[(size_t)NB * NT * NH];

// ---------------- helpers ----------------
__device__ __forceinline__ uint32_t smem_u32(const void* p) {
    uint32_t a;
    asm("{ .reg .u64 t; cvta.to.shared.u64 t, %1; cvt.u32.u64 %0, t; }" : "=r"(a) : "l"(p));
    return a;
}
__device__ __forceinline__ int swoff(int row, int k, int K) {
    return row * K * 2 + ((((k >> 3) ^ (row & 7)) << 4) | ((k & 7) << 1));
}
__device__ __forceinline__ uint32_t bf2_bits(float a, float b) {
    __nv_bfloat162 h = __floats2bfloat162_rn(a, b);
    return *reinterpret_cast<uint32_t*>(&h);
}
__device__ __forceinline__ ull ffma2(ull a, ull b, ull c) {
    ull d;
    asm("fma.rn.f32x2 %0, %1, %2, %3;" : "=l"(d) : "l"(a), "l"(b), "l"(c));
    return d;
}
__device__ __forceinline__ float f32x2_sum(ull a) {
    float lo, hi;
    asm("mov.b64 {%0, %1}, %2;" : "=f"(lo), "=f"(hi) : "l"(a));
    return lo + hi;
}
__device__ __forceinline__ ull pack2(float lo, float hi) {
    ull u;
    asm("mov.b64 %0, {%1, %2};" : "=l"(u) : "f"(lo), "f"(hi));
    return u;
}
__device__ __forceinline__ float tanhapx(float x) {
    float y;
    asm("tanh.approx.f32 %0, %1;" : "=f"(y) : "f"(x));
    return y;
}

__device__ __forceinline__ void ldsm_x4(uint32_t* r, uint32_t addr) {
    asm volatile("ldmatrix.sync.aligned.m8n8.x4.shared.b16 {%0,%1,%2,%3}, [%4];"
                 : "=r"(r[0]), "=r"(r[1]), "=r"(r[2]), "=r"(r[3]) : "r"(addr));
}
__device__ __forceinline__ void ldsm_x2(uint32_t* r, uint32_t addr) {
    asm volatile("ldmatrix.sync.aligned.m8n8.x2.shared.b16 {%0,%1}, [%2];"
                 : "=r"(r[0]), "=r"(r[1]) : "r"(addr));
}
__device__ __forceinline__ void mma_bf16(float* c, const uint32_t* a, const uint32_t* b) {
    asm volatile(
        "mma.sync.aligned.m16n8k16.row.col.f32.bf16.bf16.f32 "
        "{%0,%1,%2,%3}, {%4,%5,%6,%7}, {%8,%9}, {%0,%1,%2,%3};"
        : "+f"(c[0]), "+f"(c[1]), "+f"(c[2]), "+f"(c[3])
        : "r"(a[0]), "r"(a[1]), "r"(a[2]), "r"(a[3]), "r"(b[0]), "r"(b[1]));
}

// ---------------- gx GEMM (exact R15 best: A-resident + W double-buffer + frag reuse) ----------------
template <int K>
__global__ __launch_bounds__(256, 1)
void gemm_mma(const float* __restrict__ A, const float* __restrict__ W,
              const float* __restrict__ bih, int mb_off) {
    extern __shared__ char sm[];
    constexpr int TILE = 128 * K * 2;
    constexpr int NF4  = (128 * (K / 4)) / 256;
    char* Ahi = sm;
    char* Alo = Ahi + TILE;
    char* Wbuf[2][2] = { { Alo + TILE,     Alo + 2 * TILE },
                         { Alo + 3 * TILE, Alo + 4 * TILE } };

    const int tid = threadIdx.x;
    const int wid = tid >> 5, lane = tid & 31;
    const int mb = blockIdx.x + mb_off;
    const int warp_m = wid >> 2;
    const int warp_n = wid & 3;

    {
        const float4* Ag = reinterpret_cast<const float4*>(A + (size_t)mb * 128 * K);
        #pragma unroll
        for (int p = 0; p < NF4; ++p) {
            int idx = tid + p * 256;
            int m = idx / (K / 4);
            int k = (idx % (K / 4)) * 4;
            float4 v = Ag[idx];
            float h0 = __bfloat162float(__float2bfloat16(v.x));
            float h1 = __bfloat162float(__float2bfloat16(v.y));
            float h2 = __bfloat162float(__float2bfloat16(v.z));
            float h3 = __bfloat162float(__float2bfloat16(v.w));
            int sw = swoff(m, k, K);
            *reinterpret_cast<uint2*>(Ahi + sw) =
                make_uint2(bf2_bits(v.x, v.y), bf2_bits(v.z, v.w));
            *reinterpret_cast<uint2*>(Alo + sw) =
                make_uint2(bf2_bits(v.x - h0, v.y - h1), bf2_bits(v.z - h2, v.w - h3));
        }
    }
    {
        const float4* Wg = reinterpret_cast<const float4*>(W);
        #pragma unroll
        for (int p = 0; p < NF4; ++p) {
            int idx = tid + p * 256;
            int n = idx / (K / 4);
            int k = (idx % (K / 4)) * 4;
            float4 v = Wg[idx];
            float h0 = __bfloat162float(__float2bfloat16(v.x));
            float h1 = __bfloat162float(__float2bfloat16(v.y));
            float h2 = __bfloat162float(__float2bfloat16(v.z));
            float h3 = __bfloat162float(__float2bfloat16(v.w));
            int sw = swoff(n, k, K);
            *reinterpret_cast<uint2*>(Wbuf[0][0] + sw) =
                make_uint2(bf2_bits(v.x, v.y), bf2_bits(v.z, v.w));
            *reinterpret_cast<uint2*>(Wbuf[0][1] + sw) =
                make_uint2(bf2_bits(v.x - h0, v.y - h1), bf2_bits(v.z - h2, v.w - h3));
        }
    }
    __syncthreads();

    const int gr = lane >> 2, gc = (lane & 3) * 2;

    for (int nb = 0; nb < 3; ++nb) {
        const char* Wh = Wbuf[nb & 1][0];
        const char* Wl = Wbuf[nb & 1][1];

        float4 wpre[NF4];
        if (nb < 2) {
            const float4* Wg = reinterpret_cast<const float4*>(W + (size_t)(nb + 1) * 128 * K);
            #pragma unroll
            for (int p = 0; p < NF4; ++p) wpre[p] = Wg[tid + p * 256];
        }

        float acc[4][4][4];
        #pragma unroll
        for (int i = 0; i < 4; ++i)
            #pragma unroll
            for (int j = 0; j < 4; ++j)
                #pragma unroll
                for (int q = 0; q < 4; ++q) acc[i][j][q] = 0.f;

        #pragma unroll
        for (int kk = 0; kk < K / 16; ++kk) {
            const int kb = kk * 16;
            uint32_t afh[4][4], afl[4][4], bfh[4][2], bfl[4][2];
            #pragma unroll
            for (int mf = 0; mf < 4; ++mf) {
                int row = warp_m * 64 + mf * 16 + (lane & 15);
                int so = swoff(row, kb + (lane >> 4) * 8, K);
                ldsm_x4(afh[mf], smem_u32(Ahi + so));
                ldsm_x4(afl[mf], smem_u32(Alo + so));
            }
            #pragma unroll
            for (int nf = 0; nf < 4; ++nf) {
                int rn = warp_n * 32 + nf * 8 + (lane & 7);
                int so = swoff(rn, kb + ((lane >> 3) & 1) * 8, K);
                ldsm_x2(bfh[nf], smem_u32(Wh + so));
                ldsm_x2(bfl[nf], smem_u32(Wl + so));
            }
            #pragma unroll
            for (int mf = 0; mf < 4; ++mf)
                #pragma unroll
                for (int nf = 0; nf < 4; ++nf) {
                    mma_bf16(acc[mf][nf], afh[mf], bfl[nf]);
                    mma_bf16(acc[mf][nf], afl[mf], bfh[nf]);
                    mma_bf16(acc[mf][nf], afh[mf], bfh[nf]);
                }
        }

        if (nb < 2) {
            #pragma unroll
            for (int p = 0; p < NF4; ++p) {
                int idx = tid + p * 256;
                int n = idx / (K / 4);
                int k = (idx % (K / 4)) * 4;
                float4 v = wpre[p];
                float h0 = __bfloat162float(__float2bfloat16(v.x));
                float h1 = __bfloat162float(__float2bfloat16(v.y));
                float h2 = __bfloat162float(__float2bfloat16(v.z));
                float h3 = __bfloat162float(__float2bfloat16(v.w));
                int sw = swoff(n, k, K);
                *reinterpret_cast<uint2*>(Wbuf[(nb + 1) & 1][0] + sw) =
                    make_uint2(bf2_bits(v.x, v.y), bf2_bits(v.z, v.w));
                *reinterpret_cast<uint2*>(Wbuf[(nb + 1) & 1][1] + sw) =
                    make_uint2(bf2_bits(v.x - h0, v.y - h1), bf2_bits(v.z - h2, v.w - h3));
            }
        }

        float bv[4][2];
        #pragma unroll
        for (int nf = 0; nf < 4; ++nf) {
            int col = nb * 128 + warp_n * 32 + nf * 8 + gc;
            bv[nf][0] = bih[col];
            bv[nf][1] = bih[col + 1];
        }
        #pragma unroll
        for (int mf = 0; mf < 4; ++mf) {
            int m0 = mb * 128 + warp_m * 64 + mf * 16 + gr;
            #pragma unroll
            for (int nf = 0; nf < 4; ++nf) {
                int col = nb * 128 + warp_n * 32 + nf * 8 + gc;
                float2 v0 = make_float2(acc[mf][nf][0] + bv[nf][0], acc[mf][nf][1] + bv[nf][1]);
                float2 v1 = make_float2(acc[mf][nf][2] + bv[nf][0], acc[mf][nf][3] + bv[nf][1]);
                *reinterpret_cast<float2*>(g_gx + (size_t)m0 * NG3 + col) = v0;
                *reinterpret_cast<float2*>(g_gx + (size_t)(m0 + 8) * NG3 + col) = v1;
            }
        }

        if (nb < 2) __syncthreads();
    }
}

// ---------------- GRU scan v5: fused gates, ONE barrier/step ----------------
// 256 threads: thread = (unit j = tid>>1, khalf ks = tid&1). Owns W rows
// {j, j+128, j+256} x 64-k-half in registers (192 regs). Computes r/z/n partials
// for both batches, shfl.xor(1) merges k-halves, ks==0 lane computes gates
// locally and writes h to the parity-alternating smem buffer. One BAR per step.
__global__ __launch_bounds__(256, 1)
void gru_scan_kernel(const float* __restrict__ whh, const float* __restrict__ bhh) {
    // h buffers: [parity][batch][kseg*68 + i], padded so ks=1 base shifts banks
    __shared__ __align__(16) float hs[2 * 2 * 136];

    const int tid = threadIdx.x;
    const int ks  = tid & 1;
    const int j   = tid >> 1;
    const int b0  = blockIdx.x * 2;

    // W: rows j, j+128, j+256; k in [ks*64, ks*64+64) as 32 f32x2 each
    ull wreg[3][32];
    #pragma unroll
    for (int r = 0; r < 3; ++r) {
        const float4* wp = reinterpret_cast<const float4*>(
            whh + (size_t)(r * 128 + j) * NH + ks * 64);
        #pragma unroll
        for (int f = 0; f < 16; ++f) {
            float4 v = wp[f];
            wreg[r][2 * f]     = pack2(v.x, v.y);
            wreg[r][2 * f + 1] = pack2(v.z, v.w);
        }
    }

    float br = 0.f, bz = 0.f, bn = 0.f;
    float gxr[2], gxz[2], gxn[2], hprev[2];
    const float* gp0 = g_gx + ((size_t)(b0 + 0) * NT) * NG3 + j;
    const float* gp1 = g_gx + ((size_t)(b0 + 1) * NT) * NG3 + j;
    float* ho0 = g_hseq + ((size_t)(b0 + 0) * NT) * NH + j;
    float* ho1 = g_hseq + ((size_t)(b0 + 1) * NT) * NH + j;
    hprev[0] = hprev[1] = 0.f;
    gxr[0] = gxr[1] = gxz[0] = gxz[1] = gxn[0] = gxn[1] = 0.f;

    if (ks == 0) {
        br = bhh[j]; bz = bhh[128 + j]; bn = bhh[256 + j];
        gxr[0] = gp0[0]; gxz[0] = gp0[128]; gxn[0] = gp0[256];
        gxr[1] = gp1[0]; gxz[1] = gp1[128]; gxn[1] = gp1[256];
        // init h(0) = 0 in parity-0 buffers (both batches, this unit's slot)
        hs[(0 * 2 + 0) * 136 + (j >> 6) * 68 + (j & 63)] = 0.f;
        hs[(0 * 2 + 1) * 136 + (j >> 6) * 68 + (j & 63)] = 0.f;
    }
    __syncthreads();

    for (int t = 0; t < NT; ++t) {
        const int par = t & 1;
        const ulonglong2* p0 = reinterpret_cast<const ulonglong2*>(
            hs + (par * 2 + 0) * 136 + ks * 68);
        const ulonglong2* p1 = reinterpret_cast<const ulonglong2*>(
            hs + (par * 2 + 1) * 136 + ks * 68);

        ull a[3][2];
        #pragma unroll
        for (int r = 0; r < 3; ++r) { a[r][0] = 0ULL; a[r][1] = 0ULL; }

        #pragma unroll
        for (int q = 0; q < 16; ++q) {
            ulonglong2 v0 = p0[q];
            ulonglong2 v1 = p1[q];
            #pragma unroll
            for (int r = 0; r < 3; ++r) {
                a[r][0] = ffma2(wreg[r][2 * q],     v0.x, a[r][0]);
                a[r][0] = ffma2(wreg[r][2 * q + 1], v0.y, a[r][0]);
                a[r][1] = ffma2(wreg[r][2 * q],     v1.x, a[r][1]);
                a[r][1] = ffma2(wreg[r][2 * q + 1], v1.y, a[r][1]);
            }
        }

        float s[3][2];
        #pragma unroll
        for (int r = 0; r < 3; ++r)
            #pragma unroll
            for (int b = 0; b < 2; ++b) {
                float v = f32x2_sum(a[r][b]);
                s[r][b] = v + __shfl_xor_sync(0xffffffffu, v, 1);
            }

        if (ks == 0) {
            const int np = (t + 1) & 1;
            const int hsl = (j >> 6) * 68 + (j & 63);
            #pragma unroll
            for (int b = 0; b < 2; ++b) {
                float rr = 0.5f * tanhapx(0.5f * (gxr[b] + s[0][b] + br)) + 0.5f;
                float zz = 0.5f * tanhapx(0.5f * (gxz[b] + s[1][b] + bz)) + 0.5f;
                float nn = tanhapx(gxn[b] + rr * (s[2][b] + bn));
                float hn = nn + zz * (hprev[b] - nn);
                hprev[b] = hn;
                hs[(np * 2 + b) * 136 + hsl] = hn;
                if (b == 0) ho0[(size_t)t * NH] = hn;
                else        ho1[(size_t)t * NH] = hn;
            }
            if (t + 1 < NT) {
                const float* g0 = gp0 + (size_t)(t + 1) * NG3;
                const float* g1 = gp1 + (size_t)(t + 1) * NG3;
                gxr[0] = g0[0]; gxz[0] = g0[128]; gxn[0] = g0[256];
                gxr[1] = g1[0]; gxz[1] = g1[128]; gxn[1] = g1[256];
            }
        }
        __syncthreads();
    }
}

// ---------------- final FC ----------------
__global__ void fc_kernel(const float* __restrict__ fcw, const float* __restrict__ fcb,
                          float* __restrict__ out) {
    int b = blockIdx.x;
    int w = threadIdx.x >> 5;
    int lane = threadIdx.x & 31;
    if (w >= 6) return;
    const float* last = g_hseq + ((size_t)b * NT + NT - 1) * NH;
    float s = 0.f;
    #pragma unroll
    for (int k = 0; k < 4; ++k) {
        int j = lane + 32 * k;
        s += last[j] * fcw[w * NH + j];
    }
    #pragma unroll
    for (int o = 16; o; o >>= 1) s += __shfl_down_sync(0xffffffffu, s, o);
    if (lane == 0) out[b * 6 + w] = s + fcb[w];
}

// ---------------- launch ----------------
extern "C" void kernel_launch(void* const* d_in, const int* in_sizes, int n_in,
                              void* d_out, int out_size) {
    const float* x    = (const float*)d_in[0];
    const float* wih0 = (const float*)d_in[1];
    const float* wih1 = (const float*)d_in[2];
    const float* wih2 = (const float*)d_in[3];
    const float* whh  = (const float*)d_in[4];
    const float* bih  = (const float*)d_in[5];
    const float* bhh  = (const float*)d_in[6];
    const float* fcw  = (const float*)d_in[7];
    const float* fcb  = (const float*)d_in[8];
    float* out = (float*)d_out;

    constexpr int SMEM64  = 6 * 128 * 64 * 2;    //  98304
    constexpr int SMEM128 = 6 * 128 * 128 * 2;   // 196608
    cudaFuncSetAttribute(gemm_mma<64>,  cudaFuncAttributeMaxDynamicSharedMemorySize, SMEM64);
    cudaFuncSetAttribute(gemm_mma<128>, cudaFuncAttributeMaxDynamicSharedMemorySize, SMEM128);

    float* g_hseq_ptr = nullptr;
    cudaGetSymbolAddress((void**)&g_hseq_ptr, g_hseq);

    const int ggrid = NB * NT / 128;   // 1024 CTAs

    gemm_mma<64><<<ggrid, 256, SMEM64>>>(x, wih0, bih + 0 * NG3, 0);                  // 1
    gru_scan_kernel<<<NB / 2, 256>>>(whh + 0 * NG3 * NH, bhh + 0 * NG3);              // 2
    gemm_mma<128><<<ggrid, 256, SMEM128>>>(g_hseq_ptr, wih1, bih + 1 * NG3, 0);       // 3
    gru_scan_kernel<<<NB / 2, 256>>>(whh + 1 * NG3 * NH, bhh + 1 * NG3);              // 4
    gemm_mma<128><<<512, 256, SMEM128>>>(g_hseq_ptr, wih2, bih + 2 * NG3, 0);         // 5
    gemm_mma<128><<<512, 256, SMEM128>>>(g_hseq_ptr, wih2, bih + 2 * NG3, 512);       // 6
    gru_scan_kernel<<<NB / 2, 256>>>(whh + 2 * NG3 * NH, bhh + 2 * NG3);              // 7
    fc_kernel<<<NB, 192>>>(fcw, fcb, out);                                            // 8
}